// round 1
// baseline (speedup 1.0000x reference)
#include <cuda_runtime.h>
#include <cstdint>
#include <math.h>

#define BATCH     8
#define NANCH     1047552
#define KPRE      6000
#define KOUT      1000
#define CAND_CAP  16384
#define WORDS     94          /* ceil(6000/64) */
#define WSTRIDE   96          /* padded row stride (768B, 128B-aligned) */
#define NBINS     65536

// ---------------- device scratch (static, no allocations) ----------------
__device__ __align__(128) unsigned int        g_hist[BATCH][NBINS];
__device__ __align__(128) unsigned int        g_thresh[BATCH];
__device__ __align__(128) int                 g_count[BATCH];
__device__ __align__(128) unsigned long long  g_cand[BATCH][CAND_CAP];
__device__ __align__(128) float4              g_boxes[BATCH][KPRE];
__device__ __align__(128) float               g_areas[BATCH][KPRE];
__device__ __align__(128) unsigned long long  g_mask[BATCH][KPRE][WSTRIDE];

// order-preserving float -> uint map (works for all signs)
__device__ __forceinline__ unsigned map_f32(float v) {
    unsigned b = __float_as_uint(v);
    return b ^ ((b & 0x80000000u) ? 0xFFFFFFFFu : 0x80000000u);
}

// ---------------- K0: zero hist + counts ----------------
__global__ void k_zero() {
    int idx = blockIdx.x * blockDim.x + threadIdx.x;
    const int tot = BATCH * NBINS;
    unsigned* h = &g_hist[0][0];
    for (int i = idx; i < tot; i += gridDim.x * blockDim.x) h[i] = 0u;
    if (idx < BATCH) g_count[idx] = 0;
}

// ---------------- K1: 16-bit-prefix histogram of mapped score bits ----------------
__global__ void k_hist(const float2* __restrict__ scores) {
    int b = blockIdx.y;
    const float2* sp = scores + (size_t)b * NANCH;
    for (int i = blockIdx.x * blockDim.x + threadIdx.x; i < NANCH;
         i += gridDim.x * blockDim.x) {
        unsigned m = map_f32(sp[i].y);
        atomicAdd(&g_hist[b][m >> 16], 1u);
    }
}

// ---------------- K2: find per-batch threshold bin (>= KPRE candidates) ----------------
__global__ void k_thresh() {
    int b = blockIdx.x;
    __shared__ unsigned csum[256];
    unsigned s = 0;
    int c = threadIdx.x;  // 256 threads, each sums a 256-bin chunk
    for (int k = 0; k < 256; k++) s += g_hist[b][c * 256 + k];
    csum[c] = s;
    __syncthreads();
    if (threadIdx.x == 0) {
        unsigned cum = 0;
        int chunk = 255;
        while (chunk > 0 && cum + csum[chunk] < (unsigned)KPRE) { cum += csum[chunk]; chunk--; }
        int bin = chunk * 256 + 255;
        while (bin > chunk * 256 && cum + g_hist[b][bin] < (unsigned)KPRE) { cum += g_hist[b][bin]; bin--; }
        g_thresh[b] = (unsigned)bin << 16;
    }
}

// ---------------- K3: compact candidates as 64-bit keys ----------------
__global__ void k_compact(const float2* __restrict__ scores) {
    int b = blockIdx.y;
    unsigned th = g_thresh[b];
    const float2* sp = scores + (size_t)b * NANCH;
    for (int i = blockIdx.x * blockDim.x + threadIdx.x; i < NANCH;
         i += gridDim.x * blockDim.x) {
        unsigned m = map_f32(sp[i].y);
        if (m >= th) {
            int pos = atomicAdd(&g_count[b], 1);
            if (pos < CAND_CAP)
                g_cand[b][pos] =
                    ((unsigned long long)m << 32) | (unsigned long long)(0xFFFFFFFFu - (unsigned)i);
        }
    }
}

// ---------------- K4: per-batch bitonic sort (descending) of 16384 keys ----------------
__global__ void k_sort() {
    extern __shared__ unsigned long long keys[];
    int b = blockIdx.x;
    int cnt = g_count[b];
    if (cnt > CAND_CAP) cnt = CAND_CAP;
    for (int i = threadIdx.x; i < CAND_CAP; i += blockDim.x)
        keys[i] = (i < cnt) ? g_cand[b][i] : 0ull;
    __syncthreads();
    for (int k = 2; k <= CAND_CAP; k <<= 1) {
        for (int j = k >> 1; j > 0; j >>= 1) {
            for (int i = threadIdx.x; i < CAND_CAP; i += blockDim.x) {
                int ixj = i ^ j;
                if (ixj > i) {
                    bool desc = ((i & k) == 0);
                    unsigned long long a = keys[i], c = keys[ixj];
                    bool swap = desc ? (a < c) : (a > c);
                    if (swap) { keys[i] = c; keys[ixj] = a; }
                }
            }
            __syncthreads();
        }
    }
    // write back sorted top-KPRE keys (reuse g_cand)
    for (int r = threadIdx.x; r < KPRE; r += blockDim.x)
        g_cand[b][r] = keys[r];
}

// ---------------- K5: decode boxes (apply deltas, clip), compute areas ----------------
__global__ void k_boxes(const float4* __restrict__ deltas,
                        const float4* __restrict__ anchors) {
    int b = blockIdx.y;
    int r = blockIdx.x * blockDim.x + threadIdx.x;
    if (r >= KPRE) return;
    unsigned long long key = g_cand[b][r];
    unsigned idx = 0xFFFFFFFFu - (unsigned)(key & 0xFFFFFFFFull);
    if (idx >= NANCH) idx = 0;  // defensive (shouldn't happen)
    float4 an = anchors[idx];
    float4 dl = deltas[(size_t)b * NANCH + idx];
    // deltas * RPN_BBOX_STD_DEV
    float d0 = __fmul_rn(dl.x, 0.1f);
    float d1 = __fmul_rn(dl.y, 0.1f);
    float d2 = __fmul_rn(dl.z, 0.2f);
    float d3 = __fmul_rn(dl.w, 0.2f);
    float h = __fsub_rn(an.z, an.x);
    float w = __fsub_rn(an.w, an.y);
    float cy = __fadd_rn(__fadd_rn(an.x, __fmul_rn(0.5f, h)), __fmul_rn(d0, h));
    float cx = __fadd_rn(__fadd_rn(an.y, __fmul_rn(0.5f, w)), __fmul_rn(d1, w));
    // correctly-rounded exp (match libm-quality reference)
    float e2 = (float)exp((double)d2);
    float e3 = (float)exp((double)d3);
    float h2 = __fmul_rn(h, e2);
    float w2 = __fmul_rn(w, e3);
    float y1 = __fsub_rn(cy, __fmul_rn(0.5f, h2));
    float x1 = __fsub_rn(cx, __fmul_rn(0.5f, w2));
    float y2 = __fadd_rn(y1, h2);
    float x2 = __fadd_rn(x1, w2);
    y1 = fminf(fmaxf(y1, 0.f), 1.f);
    x1 = fminf(fmaxf(x1, 0.f), 1.f);
    y2 = fminf(fmaxf(y2, 0.f), 1.f);
    x2 = fminf(fmaxf(x2, 0.f), 1.f);
    g_boxes[b][r] = make_float4(y1, x1, y2, x2);
    g_areas[b][r] = __fmul_rn(__fsub_rn(y2, y1), __fsub_rn(x2, x1));
}

// ---------------- K6: IoU suppression bitmask (upper triangle, 64x64 tiles) ----------------
__global__ void k_mask() {
    int rt = blockIdx.x, ct = blockIdx.y, b = blockIdx.z;
    if (ct < rt) return;  // lower triangle never read by the reducer
    __shared__ float4 cb[64];
    __shared__ float   ca[64];
    int t = threadIdx.x;
    int j0 = ct * 64;
    int j = j0 + t;
    if (j < KPRE) { cb[t] = g_boxes[b][j]; ca[t] = g_areas[b][j]; }
    __syncthreads();
    int i = rt * 64 + t;
    if (i >= KPRE) return;
    float4 bi = g_boxes[b][i];
    float  ai = g_areas[b][i];
    int nj = KPRE - j0;
    if (nj > 64) nj = 64;
    unsigned long long word = 0ull;
    for (int jj = 0; jj < nj; ++jj) {
        float4 bj = cb[jj];
        float yy1 = fmaxf(bi.x, bj.x);
        float xx1 = fmaxf(bi.y, bj.y);
        float yy2 = fminf(bi.z, bj.z);
        float xx2 = fminf(bi.w, bj.w);
        float dh = __fsub_rn(yy2, yy1);
        float dw = __fsub_rn(xx2, xx1);
        bool sup = false;
        if (dh > 0.f && dw > 0.f) {
            float inter = __fmul_rn(dh, dw);
            float u = __fsub_rn(__fadd_rn(ai, ca[jj]), inter);
            if (u > 0.f) {
                if (inter > __fmul_rn(0.71f, u)) {
                    sup = true;                           // definitely iou > 0.7
                } else if (inter >= __fmul_rn(0.69f, u)) {
                    sup = __fdiv_rn(inter, u) > 0.7f;     // exact boundary: match ref div
                }                                          // else definitely keep
            }
        }
        if (sup) word |= (1ull << jj);
    }
    g_mask[b][i][ct] = word;
}

// ---------------- K7: greedy reduce (1 warp per batch) + output ----------------
__global__ void k_reduce(float* __restrict__ out) {
    int b = blockIdx.x;
    int lane = threadIdx.x;
    __shared__ unsigned long long remv[WORDS];
    __shared__ int sel[KOUT];
    for (int w = lane; w < WORDS; w += 32) remv[w] = 0ull;
    __syncwarp();
    const unsigned long long* mask = &g_mask[b][0][0];

    int pf = 0;
    auto prefetch_to = [&](int upto) {
        if (upto > KPRE) upto = KPRE;
        for (; pf < upto; ++pf) {
            const char* p = (const char*)(mask + (size_t)pf * WSTRIDE);
            if (lane < 6) {
                asm volatile("prefetch.global.L1 [%0];" :: "l"(p + lane * 128));
            }
        }
    };
    prefetch_to(32);

    int cnt = 0;
    for (int w = 0; w < WORDS && cnt < KOUT; ++w) {
        unsigned long long cur = remv[w];
        unsigned long long valid = ~cur;
        if (w == WORDS - 1) valid &= (1ull << 48) - 1;  // rows 6000..6015 invalid
        while (valid) {
            int bpos = __ffsll((long long)valid) - 1;
            int i = (w << 6) + bpos;
            if (lane == 0) sel[cnt] = i;
            cnt++;
            const unsigned long long* row = mask + (size_t)i * WSTRIDE;
            unsigned long long r0 = row[lane];
            unsigned long long r1 = (lane + 32 < WORDS) ? row[lane + 32] : 0ull;
            unsigned long long r2 = (lane + 64 < WORDS) ? row[lane + 64] : 0ull;
            remv[lane] |= r0;
            if (lane + 32 < WORDS) remv[lane + 32] |= r1;
            if (lane + 64 < WORDS) remv[lane + 64] |= r2;
            // broadcast row word for the current scan word
            unsigned long long rv = (w < 32) ? r0 : ((w < 64) ? r1 : r2);
            rv = __shfl_sync(0xffffffffu, rv, w & 31);
            cur |= rv;
            unsigned long long above = (bpos == 63) ? 0ull : (~0ull << (bpos + 1));
            valid = ~cur & above;
            if (w == WORDS - 1) valid &= (1ull << 48) - 1;
            __syncwarp();
            if (cnt >= KOUT) break;
            prefetch_to(i + 32);
        }
        prefetch_to(((w + 1) << 6) + 32);
    }
    __syncwarp();

    float4* o = (float4*)(out + (size_t)b * KOUT * 4);
    for (int r = lane; r < KOUT; r += 32) {
        float4 v = make_float4(0.f, 0.f, 0.f, 0.f);
        if (r < cnt) v = g_boxes[b][sel[r]];
        o[r] = v;
    }
}

// ---------------- launch ----------------
extern "C" void kernel_launch(void* const* d_in, const int* in_sizes, int n_in,
                              void* d_out, int out_size) {
    const float2* scores  = (const float2*)d_in[0];   // (B, N, 2) f32
    const float4* deltas  = (const float4*)d_in[1];   // (B, N, 4) f32
    const float4* anchors = (const float4*)d_in[2];   // (N, 4)    f32
    float* out = (float*)d_out;                       // (B, 1000, 4) f32

    cudaFuncSetAttribute(k_sort, cudaFuncAttributeMaxDynamicSharedMemorySize,
                         CAND_CAP * (int)sizeof(unsigned long long));

    k_zero<<<512, 1024>>>();
    {
        dim3 g(512, BATCH);
        k_hist<<<g, 256>>>(scores);
    }
    k_thresh<<<BATCH, 256>>>();
    {
        dim3 g(512, BATCH);
        k_compact<<<g, 256>>>(scores);
    }
    k_sort<<<BATCH, 1024, CAND_CAP * sizeof(unsigned long long)>>>();
    {
        dim3 g((KPRE + 255) / 256, BATCH);
        k_boxes<<<g, 256>>>(deltas, anchors);
    }
    {
        dim3 g(WORDS, WORDS, BATCH);
        k_mask<<<g, 64>>>();
    }
    k_reduce<<<BATCH, 32>>>(out);
}

// round 2
// speedup vs baseline: 1.0806x; 1.0806x over previous
#include <cuda_runtime.h>
#include <cstdint>
#include <math.h>

#define BATCH     8
#define NANCH     1047552
#define KPRE      6000
#define KOUT      1000
#define CAND_CAP  16384
#define SORT_N    8192
#define HALF_N    4096
#define WORDS     94          /* ceil(6000/64) */
#define WSTRIDE   96          /* padded row stride (768B, 128B-aligned) */
#define NBINS     65536

// ---------------- device scratch (static, no allocations) ----------------
__device__ __align__(128) unsigned int        g_hist[BATCH][NBINS];
__device__ __align__(128) unsigned int        g_thresh[BATCH];
__device__ __align__(128) unsigned int        g_rth[BATCH];
__device__ __align__(128) int                 g_count[BATCH];
__device__ __align__(128) unsigned long long  g_cand[BATCH][CAND_CAP];
__device__ __align__(128) unsigned long long  g_cand2[BATCH][SORT_N];
__device__ __align__(128) float4              g_boxes[BATCH][KPRE];
__device__ __align__(128) float               g_areas[BATCH][KPRE];
__device__ __align__(128) unsigned long long  g_mask[BATCH][KPRE][WSTRIDE];

// order-preserving float -> uint map (works for all signs)
__device__ __forceinline__ unsigned map_f32(float v) {
    unsigned b = __float_as_uint(v);
    return b ^ ((b & 0x80000000u) ? 0xFFFFFFFFu : 0x80000000u);
}

// ---------------- K0: zero hist + counts ----------------
__global__ void k_zero() {
    int idx = blockIdx.x * blockDim.x + threadIdx.x;
    const int tot = BATCH * NBINS;
    unsigned* h = &g_hist[0][0];
    for (int i = idx; i < tot; i += gridDim.x * blockDim.x) h[i] = 0u;
    if (idx < BATCH) g_count[idx] = 0;
}

// ---------------- K1: 16-bit-prefix histogram (float4 = 2 anchors / load) ----------------
__global__ void k_hist(const float4* __restrict__ scores4) {
    int b = blockIdx.y;
    const float4* sp = scores4 + (size_t)b * (NANCH / 2);
    const int M = NANCH / 2;
    int stride = gridDim.x * blockDim.x;
    int tid = blockIdx.x * blockDim.x + threadIdx.x;
    #pragma unroll 4
    for (int i = tid; i < M; i += stride) {
        float4 v = sp[i];
        atomicAdd(&g_hist[b][map_f32(v.y) >> 16], 1u);
        atomicAdd(&g_hist[b][map_f32(v.w) >> 16], 1u);
    }
}

// ---------------- K2: coarse threshold bin (>= KPRE candidates) ----------------
__global__ void k_thresh() {
    int b = blockIdx.x;
    __shared__ unsigned csum[256];
    unsigned s = 0;
    int c = threadIdx.x;
    for (int k = 0; k < 256; k++) s += g_hist[b][c * 256 + k];
    csum[c] = s;
    __syncthreads();
    if (threadIdx.x == 0) {
        unsigned cum = 0;
        int chunk = 255;
        while (chunk > 0 && cum + csum[chunk] < (unsigned)KPRE) { cum += csum[chunk]; chunk--; }
        int bin = chunk * 256 + 255;
        while (bin > chunk * 256 && cum + g_hist[b][bin] < (unsigned)KPRE) { cum += g_hist[b][bin]; bin--; }
        g_thresh[b] = (unsigned)bin << 16;
    }
}

// ---------------- K3: compact candidates (warp-aggregated atomics) ----------------
__global__ void k_compact(const float4* __restrict__ scores4) {
    int b = blockIdx.y;
    unsigned th = g_thresh[b];
    const float4* sp = scores4 + (size_t)b * (NANCH / 2);
    const int M = NANCH / 2;
    int stride = gridDim.x * blockDim.x;
    int tid = blockIdx.x * blockDim.x + threadIdx.x;
    int bound = ((M + stride - 1) / stride) * stride;
    unsigned lanebit = 1u << (threadIdx.x & 31);
    for (int i = tid; i < bound; i += stride) {
        unsigned m0 = 0, m1 = 0;
        bool in = i < M;
        if (in) {
            float4 v = sp[i];
            m0 = map_f32(v.y);
            m1 = map_f32(v.w);
        }
        bool p0 = in && m0 >= th;
        bool p1 = in && m1 >= th;
        unsigned b0 = __ballot_sync(0xffffffffu, p0);
        unsigned b1 = __ballot_sync(0xffffffffu, p1);
        int c0 = __popc(b0), c1 = __popc(b1);
        int base = 0;
        if (c0 + c1) {
            if ((threadIdx.x & 31) == 0 && (c0 + c1))
                base = atomicAdd(&g_count[b], c0 + c1);
            base = __shfl_sync(0xffffffffu, base, 0);
            if (p0) {
                int pos = base + __popc(b0 & (lanebit - 1));
                if (pos < CAND_CAP)
                    g_cand[b][pos] = ((unsigned long long)m0 << 32) |
                                     (unsigned long long)(0xFFFFFFFFu - (unsigned)(2 * i));
            }
            if (p1) {
                int pos = base + c0 + __popc(b1 & (lanebit - 1));
                if (pos < CAND_CAP)
                    g_cand[b][pos] = ((unsigned long long)m1 << 32) |
                                     (unsigned long long)(0xFFFFFFFFu - (unsigned)(2 * i + 1));
            }
        }
    }
}

// ---------------- K4: refine threshold to 24-bit prefix; compact into g_cand2 ----------------
__global__ void k_refine() {
    int b = blockIdx.x;
    __shared__ unsigned h[256];
    __shared__ unsigned above;
    __shared__ int pos;
    __shared__ unsigned s_rth;
    int cnt = g_count[b];
    if (cnt > CAND_CAP) cnt = CAND_CAP;
    unsigned cbhi = g_thresh[b];
    if (threadIdx.x < 256) h[threadIdx.x] = 0;
    if (threadIdx.x == 0) { above = 0; pos = 0; }
    __syncthreads();
    for (int i = threadIdx.x; i < cnt; i += blockDim.x) {
        unsigned m = (unsigned)(g_cand[b][i] >> 32);
        if (m >= cbhi + 0x10000u) atomicAdd(&above, 1u);
        else atomicAdd(&h[(m >> 8) & 0xFF], 1u);
    }
    __syncthreads();
    if (threadIdx.x == 0) {
        unsigned cum = above;
        int sb = 255;
        while (sb > 0 && cum + h[sb] < (unsigned)KPRE) { cum += h[sb]; sb--; }
        s_rth = cbhi + ((unsigned)sb << 8);
        g_rth[b] = s_rth;
    }
    __syncthreads();
    // zero-pad destination, then compact survivors
    for (int i = threadIdx.x; i < SORT_N; i += blockDim.x) g_cand2[b][i] = 0ull;
    __syncthreads();
    unsigned th = s_rth;
    int bound = ((cnt + blockDim.x - 1) / blockDim.x) * blockDim.x;
    unsigned lanebit = 1u << (threadIdx.x & 31);
    for (int i = threadIdx.x; i < bound; i += blockDim.x) {
        unsigned long long key = (i < cnt) ? g_cand[b][i] : 0ull;
        bool p = (i < cnt) && ((unsigned)(key >> 32) >= th);
        unsigned bl = __ballot_sync(0xffffffffu, p);
        int base = 0;
        if (bl) {
            if ((threadIdx.x & 31) == 0) base = atomicAdd(&pos, __popc(bl));
            base = __shfl_sync(0xffffffffu, base, 0);
            if (p) {
                int o = base + __popc(bl & (lanebit - 1));
                if (o < SORT_N) g_cand2[b][o] = key;
            }
        }
    }
}

// ---------------- K5: per-half bitonic sort (descending) of 4096 keys ----------------
__global__ void k_sortA() {
    __shared__ unsigned long long keys[HALF_N];
    int b = blockIdx.y;
    int half = blockIdx.x;
    unsigned long long* src = &g_cand2[b][half * HALF_N];
    for (int i = threadIdx.x; i < HALF_N; i += blockDim.x) keys[i] = src[i];
    __syncthreads();
    for (int k = 2; k <= HALF_N; k <<= 1) {
        for (int j = k >> 1; j > 0; j >>= 1) {
            #pragma unroll
            for (int u = 0; u < HALF_N / 1024; u++) {
                int i = threadIdx.x + u * 1024;
                int ixj = i ^ j;
                if (ixj > i) {
                    bool desc = ((i & k) == 0);
                    unsigned long long a = keys[i], c = keys[ixj];
                    bool swap = desc ? (a < c) : (a > c);
                    if (swap) { keys[i] = c; keys[ixj] = a; }
                }
            }
            __syncthreads();
        }
    }
    for (int i = threadIdx.x; i < HALF_N; i += blockDim.x) src[i] = keys[i];
}

// ---------------- K6: bitonic merge of two descending 4096-halves -> top KPRE ----------------
__global__ void k_merge() {
    extern __shared__ unsigned long long keys[];
    int b = blockIdx.x;
    for (int i = threadIdx.x; i < HALF_N; i += blockDim.x) {
        keys[i] = g_cand2[b][i];
        keys[HALF_N + i] = g_cand2[b][SORT_N - 1 - i];  // reverse 2nd half -> bitonic
    }
    __syncthreads();
    for (int j = SORT_N >> 1; j > 0; j >>= 1) {
        #pragma unroll
        for (int u = 0; u < SORT_N / 1024; u++) {
            int i = threadIdx.x + u * 1024;
            int ixj = i ^ j;
            if (ixj > i) {
                unsigned long long a = keys[i], c = keys[ixj];
                if (a < c) { keys[i] = c; keys[ixj] = a; }  // descending
            }
        }
        __syncthreads();
    }
    for (int r = threadIdx.x; r < KPRE; r += blockDim.x) g_cand[b][r] = keys[r];
}

// ---------------- K7: decode boxes (apply deltas, clip), compute areas ----------------
__global__ void k_boxes(const float4* __restrict__ deltas,
                        const float4* __restrict__ anchors) {
    int b = blockIdx.y;
    int r = blockIdx.x * blockDim.x + threadIdx.x;
    if (r >= KPRE) return;
    unsigned long long key = g_cand[b][r];
    unsigned idx = 0xFFFFFFFFu - (unsigned)(key & 0xFFFFFFFFull);
    if (idx >= NANCH) idx = 0;
    float4 an = anchors[idx];
    float4 dl = deltas[(size_t)b * NANCH + idx];
    float d0 = __fmul_rn(dl.x, 0.1f);
    float d1 = __fmul_rn(dl.y, 0.1f);
    float d2 = __fmul_rn(dl.z, 0.2f);
    float d3 = __fmul_rn(dl.w, 0.2f);
    float h = __fsub_rn(an.z, an.x);
    float w = __fsub_rn(an.w, an.y);
    float cy = __fadd_rn(__fadd_rn(an.x, __fmul_rn(0.5f, h)), __fmul_rn(d0, h));
    float cx = __fadd_rn(__fadd_rn(an.y, __fmul_rn(0.5f, w)), __fmul_rn(d1, w));
    float e2 = (float)exp((double)d2);
    float e3 = (float)exp((double)d3);
    float h2 = __fmul_rn(h, e2);
    float w2 = __fmul_rn(w, e3);
    float y1 = __fsub_rn(cy, __fmul_rn(0.5f, h2));
    float x1 = __fsub_rn(cx, __fmul_rn(0.5f, w2));
    float y2 = __fadd_rn(y1, h2);
    float x2 = __fadd_rn(x1, w2);
    y1 = fminf(fmaxf(y1, 0.f), 1.f);
    x1 = fminf(fmaxf(x1, 0.f), 1.f);
    y2 = fminf(fmaxf(y2, 0.f), 1.f);
    x2 = fminf(fmaxf(x2, 0.f), 1.f);
    g_boxes[b][r] = make_float4(y1, x1, y2, x2);
    g_areas[b][r] = __fmul_rn(__fsub_rn(y2, y1), __fsub_rn(x2, x1));
}

// ---------------- K8: IoU suppression bitmask (upper triangle, 64x64 tiles) ----------------
__global__ void k_mask() {
    int rt = blockIdx.x, ct = blockIdx.y, b = blockIdx.z;
    if (ct < rt) return;
    __shared__ float4 cb[64];
    __shared__ float  ca[64];
    int t = threadIdx.x;
    int j0 = ct * 64;
    int j = j0 + t;
    if (j < KPRE) { cb[t] = g_boxes[b][j]; ca[t] = g_areas[b][j]; }
    __syncthreads();
    int i = rt * 64 + t;
    if (i >= KPRE) return;
    float4 bi = g_boxes[b][i];
    float  ai = g_areas[b][i];
    int nj = KPRE - j0;
    if (nj > 64) nj = 64;
    unsigned long long word = 0ull;
    for (int jj = 0; jj < nj; ++jj) {
        float4 bj = cb[jj];
        float yy1 = fmaxf(bi.x, bj.x);
        float xx1 = fmaxf(bi.y, bj.y);
        float yy2 = fminf(bi.z, bj.z);
        float xx2 = fminf(bi.w, bj.w);
        float dh = __fsub_rn(yy2, yy1);
        float dw = __fsub_rn(xx2, xx1);
        bool sup = false;
        if (dh > 0.f && dw > 0.f) {
            float inter = __fmul_rn(dh, dw);
            float u = __fsub_rn(__fadd_rn(ai, ca[jj]), inter);
            if (u > 0.f) {
                if (inter > __fmul_rn(0.71f, u)) {
                    sup = true;
                } else if (inter >= __fmul_rn(0.69f, u)) {
                    sup = __fdiv_rn(inter, u) > 0.7f;
                }
            }
        }
        if (sup) word |= (1ull << jj);
    }
    g_mask[b][i][ct] = word;
}

// ---------------- K9: greedy reduce (1 warp per batch), remv in registers ----------------
__global__ void k_reduce(float* __restrict__ out) {
    int b = blockIdx.x;
    int lane = threadIdx.x;
    __shared__ int sel[KOUT];
    unsigned long long rm0 = 0ull, rm1 = 0ull, rm2 = 0ull;
    const unsigned long long* mask = &g_mask[b][0][0];
    int cnt = 0;

    for (int w = 0; w < WORDS && cnt < KOUT; ++w) {
        int slot = w >> 5;
        int owner = w & 31;
        unsigned long long rmv = (slot == 0) ? rm0 : ((slot == 1) ? rm1 : rm2);
        unsigned long long cur = __shfl_sync(0xffffffffu, rmv, owner);
        unsigned long long wm = (w == WORDS - 1) ? ((1ull << 48) - 1) : ~0ull;
        unsigned long long valid = ~cur & wm;

        // prefetch rows of the first few candidates in this word
        {
            unsigned long long v2 = valid;
            #pragma unroll
            for (int c = 0; c < 4; c++) {
                if (!v2) break;
                int nb = __ffsll((long long)v2) - 1;
                v2 &= v2 - 1;
                const char* p = (const char*)(mask + (size_t)((w << 6) + nb) * WSTRIDE);
                if ((lane >> 3) == c && (lane & 7) < 6)
                    asm volatile("prefetch.global.L1 [%0];" :: "l"(p + (lane & 7) * 128));
            }
        }

        while (valid) {
            int bpos = __ffsll((long long)valid) - 1;
            int i = (w << 6) + bpos;
            if (lane == 0) sel[cnt] = i;
            cnt++;
            if (cnt >= KOUT) break;
            const unsigned long long* row = mask + (size_t)i * WSTRIDE;
            unsigned long long r0 = __ldg(row + lane);
            unsigned long long r1 = __ldg(row + lane + 32);
            unsigned long long r2 = (lane + 64 < WORDS) ? __ldg(row + lane + 64) : 0ull;
            rm0 |= r0;
            rm1 |= r1;
            rm2 |= r2;
            unsigned long long rw = (slot == 0) ? r0 : ((slot == 1) ? r1 : r2);
            cur |= __shfl_sync(0xffffffffu, rw, owner);
            unsigned long long above = (bpos == 63) ? 0ull : (~0ull << (bpos + 1));
            valid = ~cur & wm & above;

            // speculative prefetch of next candidates' rows
            unsigned long long v2 = valid;
            #pragma unroll
            for (int c = 0; c < 4; c++) {
                if (!v2) break;
                int nb = __ffsll((long long)v2) - 1;
                v2 &= v2 - 1;
                const char* p = (const char*)(mask + (size_t)((w << 6) + nb) * WSTRIDE);
                if ((lane >> 3) == c && (lane & 7) < 6)
                    asm volatile("prefetch.global.L1 [%0];" :: "l"(p + (lane & 7) * 128));
            }
        }
    }
    __syncwarp();

    float4* o = (float4*)(out + (size_t)b * KOUT * 4);
    for (int r = lane; r < KOUT; r += 32) {
        float4 v = make_float4(0.f, 0.f, 0.f, 0.f);
        if (r < cnt) v = g_boxes[b][sel[r]];
        o[r] = v;
    }
}

// ---------------- launch ----------------
extern "C" void kernel_launch(void* const* d_in, const int* in_sizes, int n_in,
                              void* d_out, int out_size) {
    const float4* scores4 = (const float4*)d_in[0];  // (B, N, 2) f32 viewed as float4 pairs
    const float4* deltas  = (const float4*)d_in[1];  // (B, N, 4) f32
    const float4* anchors = (const float4*)d_in[2];  // (N, 4)    f32
    float* out = (float*)d_out;                      // (B, 1000, 4) f32

    cudaFuncSetAttribute(k_merge, cudaFuncAttributeMaxDynamicSharedMemorySize,
                         SORT_N * (int)sizeof(unsigned long long));

    k_zero<<<512, 1024>>>();
    {
        dim3 g(256, BATCH);
        k_hist<<<g, 256>>>(scores4);
    }
    k_thresh<<<BATCH, 256>>>();
    {
        dim3 g(256, BATCH);
        k_compact<<<g, 256>>>(scores4);
    }
    k_refine<<<BATCH, 256>>>();
    {
        dim3 g(2, BATCH);
        k_sortA<<<g, 1024>>>();
    }
    k_merge<<<BATCH, 1024, SORT_N * sizeof(unsigned long long)>>>();
    {
        dim3 g((KPRE + 255) / 256, BATCH);
        k_boxes<<<g, 256>>>(deltas, anchors);
    }
    {
        dim3 g(WORDS, WORDS, BATCH);
        k_mask<<<g, 64>>>();
    }
    k_reduce<<<BATCH, 32>>>(out);
}

// round 3
// speedup vs baseline: 1.1502x; 1.0644x over previous
#include <cuda_runtime.h>
#include <cstdint>
#include <math.h>

#define BATCH     8
#define NANCH     1047552
#define KPRE      6000
#define KOUT      1000
#define CAND_CAP  16384
#define SORT_N    8192
#define HALF_N    4096
#define WORDS     94          /* ceil(6000/64) */
#define WSTRIDE   96          /* padded row stride (768B, 128B-aligned) */
#define NBINS     65536
#define TILES     94          /* 94*64 = 6016 sorted slots */
#define NSLOT     (TILES*64)

// ---------------- device scratch (static, no allocations) ----------------
__device__ __align__(128) unsigned int        g_hist[BATCH][NBINS];
__device__ __align__(128) unsigned int        g_thresh[BATCH];
__device__ __align__(128) int                 g_count[BATCH];
__device__ __align__(128) unsigned long long  g_cand[BATCH][CAND_CAP];
__device__ __align__(128) unsigned long long  g_cand2[BATCH][SORT_N];
__device__ __align__(128) float4              g_boxes[BATCH][KPRE];
__device__ __align__(128) float               g_areas[BATCH][KPRE];
__device__ __align__(128) unsigned long long  g_mask[BATCH][KPRE][WSTRIDE];
// spatial structures
__device__ __align__(128) float4              g_sbox[BATCH][NSLOT];
__device__ __align__(128) float               g_sarea[BATCH][NSLOT];
__device__ __align__(128) int                 g_srank[BATCH][NSLOT];
__device__ __align__(128) float4              g_aabb[BATCH][TILES];

__device__ __forceinline__ unsigned map_f32(float v) {
    unsigned b = __float_as_uint(v);
    return b ^ ((b & 0x80000000u) ? 0xFFFFFFFFu : 0x80000000u);
}

// ---------------- K0: zero hist + counts + mask ----------------
__global__ void k_zero() {
    int idx = blockIdx.x * blockDim.x + threadIdx.x;
    int stride = gridDim.x * blockDim.x;
    const int tot = BATCH * NBINS;
    unsigned* h = &g_hist[0][0];
    for (int i = idx; i < tot; i += stride) h[i] = 0u;
    if (idx < BATCH) g_count[idx] = 0;
    unsigned long long* m = &g_mask[0][0][0];
    const int mtot = BATCH * KPRE * WSTRIDE;
    for (int i = idx; i < mtot; i += stride) m[i] = 0ull;
}

// ---------------- K1: 16-bit-prefix histogram ----------------
__global__ void k_hist(const float4* __restrict__ scores4) {
    int b = blockIdx.y;
    const float4* sp = scores4 + (size_t)b * (NANCH / 2);
    const int M = NANCH / 2;
    int stride = gridDim.x * blockDim.x;
    int tid = blockIdx.x * blockDim.x + threadIdx.x;
    #pragma unroll 4
    for (int i = tid; i < M; i += stride) {
        float4 v = sp[i];
        atomicAdd(&g_hist[b][map_f32(v.y) >> 16], 1u);
        atomicAdd(&g_hist[b][map_f32(v.w) >> 16], 1u);
    }
}

// ---------------- K2: coarse threshold ----------------
__global__ void k_thresh() {
    int b = blockIdx.x;
    __shared__ unsigned csum[256];
    unsigned s = 0;
    int c = threadIdx.x;
    for (int k = 0; k < 256; k++) s += g_hist[b][c * 256 + k];
    csum[c] = s;
    __syncthreads();
    if (threadIdx.x == 0) {
        unsigned cum = 0;
        int chunk = 255;
        while (chunk > 0 && cum + csum[chunk] < (unsigned)KPRE) { cum += csum[chunk]; chunk--; }
        int bin = chunk * 256 + 255;
        while (bin > chunk * 256 && cum + g_hist[b][bin] < (unsigned)KPRE) { cum += g_hist[b][bin]; bin--; }
        g_thresh[b] = (unsigned)bin << 16;
    }
}

// ---------------- K3: compact candidates ----------------
__global__ void k_compact(const float4* __restrict__ scores4) {
    int b = blockIdx.y;
    unsigned th = g_thresh[b];
    const float4* sp = scores4 + (size_t)b * (NANCH / 2);
    const int M = NANCH / 2;
    int stride = gridDim.x * blockDim.x;
    int tid = blockIdx.x * blockDim.x + threadIdx.x;
    int bound = ((M + stride - 1) / stride) * stride;
    unsigned lanebit = 1u << (threadIdx.x & 31);
    for (int i = tid; i < bound; i += stride) {
        unsigned m0 = 0, m1 = 0;
        bool in = i < M;
        if (in) {
            float4 v = sp[i];
            m0 = map_f32(v.y);
            m1 = map_f32(v.w);
        }
        bool p0 = in && m0 >= th;
        bool p1 = in && m1 >= th;
        unsigned b0 = __ballot_sync(0xffffffffu, p0);
        unsigned b1 = __ballot_sync(0xffffffffu, p1);
        int c0 = __popc(b0), c1 = __popc(b1);
        int base = 0;
        if (c0 + c1) {
            if ((threadIdx.x & 31) == 0)
                base = atomicAdd(&g_count[b], c0 + c1);
            base = __shfl_sync(0xffffffffu, base, 0);
            if (p0) {
                int pos = base + __popc(b0 & (lanebit - 1));
                if (pos < CAND_CAP)
                    g_cand[b][pos] = ((unsigned long long)m0 << 32) |
                                     (unsigned long long)(0xFFFFFFFFu - (unsigned)(2 * i));
            }
            if (p1) {
                int pos = base + c0 + __popc(b1 & (lanebit - 1));
                if (pos < CAND_CAP)
                    g_cand[b][pos] = ((unsigned long long)m1 << 32) |
                                     (unsigned long long)(0xFFFFFFFFu - (unsigned)(2 * i + 1));
            }
        }
    }
}

// ---------------- K4: refine threshold to 24 bits; compact into g_cand2 ----------------
__global__ void k_refine() {
    int b = blockIdx.x;
    __shared__ unsigned h[256];
    __shared__ unsigned above;
    __shared__ int pos;
    __shared__ unsigned s_rth;
    int cnt = g_count[b];
    if (cnt > CAND_CAP) cnt = CAND_CAP;
    unsigned cbhi = g_thresh[b];
    if (threadIdx.x < 256) h[threadIdx.x] = 0;
    if (threadIdx.x == 0) { above = 0; pos = 0; }
    __syncthreads();
    for (int i = threadIdx.x; i < cnt; i += blockDim.x) {
        unsigned m = (unsigned)(g_cand[b][i] >> 32);
        if (m >= cbhi + 0x10000u) atomicAdd(&above, 1u);
        else atomicAdd(&h[(m >> 8) & 0xFF], 1u);
    }
    __syncthreads();
    if (threadIdx.x == 0) {
        unsigned cum = above;
        int sb = 255;
        while (sb > 0 && cum + h[sb] < (unsigned)KPRE) { cum += h[sb]; sb--; }
        s_rth = cbhi + ((unsigned)sb << 8);
    }
    __syncthreads();
    for (int i = threadIdx.x; i < SORT_N; i += blockDim.x) g_cand2[b][i] = 0ull;
    __syncthreads();
    unsigned th = s_rth;
    int bound = ((cnt + blockDim.x - 1) / blockDim.x) * blockDim.x;
    unsigned lanebit = 1u << (threadIdx.x & 31);
    for (int i = threadIdx.x; i < bound; i += blockDim.x) {
        unsigned long long key = (i < cnt) ? g_cand[b][i] : 0ull;
        bool p = (i < cnt) && ((unsigned)(key >> 32) >= th);
        unsigned bl = __ballot_sync(0xffffffffu, p);
        int base = 0;
        if (bl) {
            if ((threadIdx.x & 31) == 0) base = atomicAdd(&pos, __popc(bl));
            base = __shfl_sync(0xffffffffu, base, 0);
            if (p) {
                int o = base + __popc(bl & (lanebit - 1));
                if (o < SORT_N) g_cand2[b][o] = key;
            }
        }
    }
}

// ---------------- K5: per-half bitonic sort (descending) of 4096 keys ----------------
__global__ void k_sortA() {
    __shared__ unsigned long long keys[HALF_N];
    int b = blockIdx.y;
    int half = blockIdx.x;
    unsigned long long* src = &g_cand2[b][half * HALF_N];
    for (int i = threadIdx.x; i < HALF_N; i += blockDim.x) keys[i] = src[i];
    __syncthreads();
    for (int k = 2; k <= HALF_N; k <<= 1) {
        for (int j = k >> 1; j > 0; j >>= 1) {
            #pragma unroll
            for (int u = 0; u < HALF_N / 1024; u++) {
                int i = threadIdx.x + u * 1024;
                int ixj = i ^ j;
                if (ixj > i) {
                    bool desc = ((i & k) == 0);
                    unsigned long long a = keys[i], c = keys[ixj];
                    bool swap = desc ? (a < c) : (a > c);
                    if (swap) { keys[i] = c; keys[ixj] = a; }
                }
            }
            __syncthreads();
        }
    }
    for (int i = threadIdx.x; i < HALF_N; i += blockDim.x) src[i] = keys[i];
}

// ---------------- K6: bitonic merge of two halves -> top KPRE ----------------
__global__ void k_merge() {
    extern __shared__ unsigned long long keys[];
    int b = blockIdx.x;
    for (int i = threadIdx.x; i < HALF_N; i += blockDim.x) {
        keys[i] = g_cand2[b][i];
        keys[HALF_N + i] = g_cand2[b][SORT_N - 1 - i];
    }
    __syncthreads();
    for (int j = SORT_N >> 1; j > 0; j >>= 1) {
        #pragma unroll
        for (int u = 0; u < SORT_N / 1024; u++) {
            int i = threadIdx.x + u * 1024;
            int ixj = i ^ j;
            if (ixj > i) {
                unsigned long long a = keys[i], c = keys[ixj];
                if (a < c) { keys[i] = c; keys[ixj] = a; }
            }
        }
        __syncthreads();
    }
    for (int r = threadIdx.x; r < KPRE; r += blockDim.x) g_cand[b][r] = keys[r];
}

// ---------------- K7: decode boxes ----------------
__global__ void k_boxes(const float4* __restrict__ deltas,
                        const float4* __restrict__ anchors) {
    int b = blockIdx.y;
    int r = blockIdx.x * blockDim.x + threadIdx.x;
    if (r >= KPRE) return;
    unsigned long long key = g_cand[b][r];
    unsigned idx = 0xFFFFFFFFu - (unsigned)(key & 0xFFFFFFFFull);
    if (idx >= NANCH) idx = 0;
    float4 an = anchors[idx];
    float4 dl = deltas[(size_t)b * NANCH + idx];
    float d0 = __fmul_rn(dl.x, 0.1f);
    float d1 = __fmul_rn(dl.y, 0.1f);
    float d2 = __fmul_rn(dl.z, 0.2f);
    float d3 = __fmul_rn(dl.w, 0.2f);
    float h = __fsub_rn(an.z, an.x);
    float w = __fsub_rn(an.w, an.y);
    float cy = __fadd_rn(__fadd_rn(an.x, __fmul_rn(0.5f, h)), __fmul_rn(d0, h));
    float cx = __fadd_rn(__fadd_rn(an.y, __fmul_rn(0.5f, w)), __fmul_rn(d1, w));
    float e2 = (float)exp((double)d2);
    float e3 = (float)exp((double)d3);
    float h2 = __fmul_rn(h, e2);
    float w2 = __fmul_rn(w, e3);
    float y1 = __fsub_rn(cy, __fmul_rn(0.5f, h2));
    float x1 = __fsub_rn(cx, __fmul_rn(0.5f, w2));
    float y2 = __fadd_rn(y1, h2);
    float x2 = __fadd_rn(x1, w2);
    y1 = fminf(fmaxf(y1, 0.f), 1.f);
    x1 = fminf(fmaxf(x1, 0.f), 1.f);
    y2 = fminf(fmaxf(y2, 0.f), 1.f);
    x2 = fminf(fmaxf(x2, 0.f), 1.f);
    g_boxes[b][r] = make_float4(y1, x1, y2, x2);
    g_areas[b][r] = __fmul_rn(__fsub_rn(y2, y1), __fsub_rn(x2, x1));
}

// ---------------- K8: spatial counting sort by 8-bit Morton of center + tile AABBs ----
__global__ void k_spatial() {
    int b = blockIdx.x;
    __shared__ int hist[256];
    __shared__ int offs[256];
    __shared__ unsigned char mcell[KPRE];
    int t = threadIdx.x;
    if (t < 256) hist[t] = 0;
    __syncthreads();
    for (int r = t; r < KPRE; r += blockDim.x) {
        float4 bx = g_boxes[b][r];
        float cy = 0.5f * (bx.x + bx.z);
        float cx = 0.5f * (bx.y + bx.w);
        int iy = (int)(cy * 16.f); iy = iy < 0 ? 0 : (iy > 15 ? 15 : iy);
        int ix = (int)(cx * 16.f); ix = ix < 0 ? 0 : (ix > 15 ? 15 : ix);
        int m = 0;
        #pragma unroll
        for (int k = 0; k < 4; k++)
            m |= (((iy >> k) & 1) << (2 * k + 1)) | (((ix >> k) & 1) << (2 * k));
        mcell[r] = (unsigned char)m;
        atomicAdd(&hist[m], 1);
    }
    __syncthreads();
    if (t == 0) {
        int run = 0;
        for (int k = 0; k < 256; k++) { offs[k] = run; run += hist[k]; }
    }
    __syncthreads();
    for (int r = t; r < KPRE; r += blockDim.x) {
        int m = mcell[r];
        int pos = atomicAdd(&offs[m], 1);
        g_sbox[b][pos] = g_boxes[b][r];
        g_sarea[b][pos] = g_areas[b][r];
        g_srank[b][pos] = r;
    }
    if (t < NSLOT - KPRE) {
        int pos = KPRE + t;
        g_sbox[b][pos] = make_float4(9e9f, 9e9f, -9e9f, -9e9f);
        g_sarea[b][pos] = 0.f;
        g_srank[b][pos] = 0x7FFFFFFF;
    }
    __syncthreads();
    // per-tile AABBs (threads 0..TILES-1)
    if (t < TILES) {
        float miny = 9e9f, minx = 9e9f, maxy = -9e9f, maxx = -9e9f;
        for (int e = 0; e < 64; e++) {
            int s = t * 64 + e;
            if (g_srank[b][s] >= KPRE) continue;
            float4 bx = g_sbox[b][s];
            miny = fminf(miny, bx.x); minx = fminf(minx, bx.y);
            maxy = fmaxf(maxy, bx.z); maxx = fmaxf(maxx, bx.w);
        }
        g_aabb[b][t] = make_float4(miny, minx, maxy, maxx);
    }
}

// ---------------- K9: pair kernel — culled tiles, sparse atomic mask ----------------
__global__ void k_pairs() {
    int tA = blockIdx.x, tB = blockIdx.y, b = blockIdx.z;
    if (tB < tA) return;
    float4 aA = g_aabb[b][tA];
    float4 aB = g_aabb[b][tB];
    // strict-overlap conservative cull (pairs need dh>0 && dw>0)
    if (!(aA.z > aB.x && aB.z > aA.x && aA.w > aB.y && aB.w > aA.y)) return;

    __shared__ float4 sb4[64];
    __shared__ float  sar[64];
    __shared__ int    srk[64];
    int t = threadIdx.x;          // 128 threads: row = t&63, colhalf = t>>6
    int row = t & 63;
    int half = t >> 6;
    if (t < 64) {
        int s = tB * 64 + t;
        sb4[t] = g_sbox[b][s];
        sar[t] = g_sarea[b][s];
        srk[t] = g_srank[b][s];
    }
    __syncthreads();

    int sa = tA * 64 + row;
    int ra = g_srank[b][sa];
    if (ra >= KPRE) return;
    float4 bi = g_sbox[b][sa];
    float  ai = g_sarea[b][sa];
    // row-level cull vs tile-B AABB
    if (!(bi.z > aB.x && aB.z > bi.x && bi.w > aB.y && aB.w > bi.y)) return;

    int j0 = half * 32;
    #pragma unroll 4
    for (int jj = j0; jj < j0 + 32; ++jj) {
        if (tA == tB && jj <= row) continue;
        int rb = srk[jj];
        if (rb >= KPRE) continue;
        float4 bj = sb4[jj];
        float yy1 = fmaxf(bi.x, bj.x);
        float xx1 = fmaxf(bi.y, bj.y);
        float yy2 = fminf(bi.z, bj.z);
        float xx2 = fminf(bi.w, bj.w);
        float dh = __fsub_rn(yy2, yy1);
        float dw = __fsub_rn(xx2, xx1);
        if (dh > 0.f && dw > 0.f) {
            float inter = __fmul_rn(dh, dw);
            float u = __fsub_rn(__fadd_rn(ai, sar[jj]), inter);
            if (u > 0.f) {
                bool sup;
                if (inter > __fmul_rn(0.71f, u)) sup = true;
                else if (inter >= __fmul_rn(0.69f, u)) sup = __fdiv_rn(inter, u) > 0.7f;
                else sup = false;
                if (sup) {
                    int rmin = ra < rb ? ra : rb;
                    int rmax = ra < rb ? rb : ra;
                    atomicOr(&g_mask[b][rmin][rmax >> 6], 1ull << (rmax & 63));
                }
            }
        }
    }
}

// ---------------- K10: greedy reduce (1 warp per batch) ----------------
__global__ void k_reduce(float* __restrict__ out) {
    int b = blockIdx.x;
    int lane = threadIdx.x;
    __shared__ int sel[KOUT];
    unsigned long long rm0 = 0ull, rm1 = 0ull, rm2 = 0ull;
    const unsigned long long* mask = &g_mask[b][0][0];
    int cnt = 0;

    for (int w = 0; w < WORDS && cnt < KOUT; ++w) {
        int slot = w >> 5;
        int owner = w & 31;
        unsigned long long rmv = (slot == 0) ? rm0 : ((slot == 1) ? rm1 : rm2);
        unsigned long long cur = __shfl_sync(0xffffffffu, rmv, owner);
        unsigned long long wm = (w == WORDS - 1) ? ((1ull << 48) - 1) : ~0ull;
        unsigned long long valid = ~cur & wm;

        {
            unsigned long long v2 = valid;
            #pragma unroll
            for (int c = 0; c < 4; c++) {
                if (!v2) break;
                int nb = __ffsll((long long)v2) - 1;
                v2 &= v2 - 1;
                const char* p = (const char*)(mask + (size_t)((w << 6) + nb) * WSTRIDE);
                if ((lane >> 3) == c && (lane & 7) < 6)
                    asm volatile("prefetch.global.L1 [%0];" :: "l"(p + (lane & 7) * 128));
            }
        }

        while (valid) {
            int bpos = __ffsll((long long)valid) - 1;
            int i = (w << 6) + bpos;
            if (lane == 0) sel[cnt] = i;
            cnt++;
            if (cnt >= KOUT) break;
            const unsigned long long* row = mask + (size_t)i * WSTRIDE;
            unsigned long long r0 = __ldg(row + lane);
            unsigned long long r1 = __ldg(row + lane + 32);
            unsigned long long r2 = (lane + 64 < WORDS) ? __ldg(row + lane + 64) : 0ull;
            rm0 |= r0;
            rm1 |= r1;
            rm2 |= r2;
            unsigned long long rw = (slot == 0) ? r0 : ((slot == 1) ? r1 : r2);
            cur |= __shfl_sync(0xffffffffu, rw, owner);
            unsigned long long above = (bpos == 63) ? 0ull : (~0ull << (bpos + 1));
            valid = ~cur & wm & above;

            unsigned long long v2 = valid;
            #pragma unroll
            for (int c = 0; c < 4; c++) {
                if (!v2) break;
                int nb = __ffsll((long long)v2) - 1;
                v2 &= v2 - 1;
                const char* p = (const char*)(mask + (size_t)((w << 6) + nb) * WSTRIDE);
                if ((lane >> 3) == c && (lane & 7) < 6)
                    asm volatile("prefetch.global.L1 [%0];" :: "l"(p + (lane & 7) * 128));
            }
        }
    }
    __syncwarp();

    float4* o = (float4*)(out + (size_t)b * KOUT * 4);
    for (int r = lane; r < KOUT; r += 32) {
        float4 v = make_float4(0.f, 0.f, 0.f, 0.f);
        if (r < cnt) v = g_boxes[b][sel[r]];
        o[r] = v;
    }
}

// ---------------- launch ----------------
extern "C" void kernel_launch(void* const* d_in, const int* in_sizes, int n_in,
                              void* d_out, int out_size) {
    const float4* scores4 = (const float4*)d_in[0];
    const float4* deltas  = (const float4*)d_in[1];
    const float4* anchors = (const float4*)d_in[2];
    float* out = (float*)d_out;

    cudaFuncSetAttribute(k_merge, cudaFuncAttributeMaxDynamicSharedMemorySize,
                         SORT_N * (int)sizeof(unsigned long long));

    k_zero<<<1024, 1024>>>();
    {
        dim3 g(256, BATCH);
        k_hist<<<g, 256>>>(scores4);
    }
    k_thresh<<<BATCH, 256>>>();
    {
        dim3 g(256, BATCH);
        k_compact<<<g, 256>>>(scores4);
    }
    k_refine<<<BATCH, 256>>>();
    {
        dim3 g(2, BATCH);
        k_sortA<<<g, 1024>>>();
    }
    k_merge<<<BATCH, 1024, SORT_N * sizeof(unsigned long long)>>>();
    {
        dim3 g((KPRE + 255) / 256, BATCH);
        k_boxes<<<g, 256>>>(deltas, anchors);
    }
    k_spatial<<<BATCH, 256>>>();
    {
        dim3 g(TILES, TILES, BATCH);
        k_pairs<<<g, 128>>>();
    }
    k_reduce<<<BATCH, 32>>>(out);
}

// round 5
// speedup vs baseline: 2.0184x; 1.7549x over previous
#include <cuda_runtime.h>
#include <cstdint>
#include <math.h>

#define BATCH     8
#define NANCH     1047552
#define KPRE      6000
#define KOUT      1000
#define CAND_CAP  16384
#define SORT_N    8192
#define CHUNK     256
#define NCHUNK    (SORT_N / CHUNK)
#define WORDS     94          /* ceil(6000/64) */
#define WSTRIDE   96          /* padded row stride (768B, 128B-aligned) */
#define NBINS     65536
#define TILES     94          /* 94*64 = 6016 sorted slots */
#define NSLOT     (TILES*64)

typedef unsigned long long u64;

// ---------------- device scratch (static, no allocations) ----------------
__device__ __align__(128) unsigned int g_hist[BATCH][NBINS];
__device__ __align__(128) unsigned int g_thresh[BATCH];
__device__ __align__(128) int          g_count[BATCH];
__device__ __align__(128) u64          g_cand[BATCH][CAND_CAP];
__device__ __align__(128) u64          g_cand2[BATCH][SORT_N];
__device__ __align__(128) float4       g_boxes[BATCH][KPRE];
__device__ __align__(128) float        g_areas[BATCH][KPRE];
__device__ __align__(128) u64          g_mask[BATCH][KPRE][WSTRIDE];
__device__ __align__(128) u64          g_rowbits[BATCH][WSTRIDE];
// spatial structures
__device__ __align__(128) float4       g_sbox[BATCH][NSLOT];
__device__ __align__(128) float        g_sarea[BATCH][NSLOT];
__device__ __align__(128) int          g_srank[BATCH][NSLOT];
__device__ __align__(128) float4       g_aabb[BATCH][TILES];

__device__ __forceinline__ unsigned map_f32(float v) {
    unsigned b = __float_as_uint(v);
    return b ^ ((b & 0x80000000u) ? 0xFFFFFFFFu : 0x80000000u);
}

// ---------------- K0: zero hist + counts + mask + rowbits ----------------
__global__ void k_zero() {
    int idx = blockIdx.x * blockDim.x + threadIdx.x;
    int stride = gridDim.x * blockDim.x;
    const int tot = BATCH * NBINS;
    unsigned* h = &g_hist[0][0];
    for (int i = idx; i < tot; i += stride) h[i] = 0u;
    if (idx < BATCH) g_count[idx] = 0;
    u64* m = &g_mask[0][0][0];
    const int mtot = BATCH * KPRE * WSTRIDE;
    for (int i = idx; i < mtot; i += stride) m[i] = 0ull;
    u64* rb = &g_rowbits[0][0];
    const int rtot = BATCH * WSTRIDE;
    for (int i = idx; i < rtot; i += stride) rb[i] = 0ull;
}

// ---------------- K1: 16-bit-prefix histogram (4-way ILP) ----------------
__global__ void k_hist(const float4* __restrict__ scores4) {
    int b = blockIdx.y;
    const float4* sp = scores4 + (size_t)b * (NANCH / 2);
    const int M = NANCH / 2;
    int S = gridDim.x * blockDim.x;
    int tid = blockIdx.x * blockDim.x + threadIdx.x;
    for (int i = tid; i < M; i += 4 * S) {
        bool h1 = i + S < M, h2 = i + 2 * S < M, h3 = i + 3 * S < M;
        float4 v0 = sp[i];
        float4 v1 = h1 ? sp[i + S] : make_float4(0, 0, 0, 0);
        float4 v2 = h2 ? sp[i + 2 * S] : make_float4(0, 0, 0, 0);
        float4 v3 = h3 ? sp[i + 3 * S] : make_float4(0, 0, 0, 0);
        atomicAdd(&g_hist[b][map_f32(v0.y) >> 16], 1u);
        atomicAdd(&g_hist[b][map_f32(v0.w) >> 16], 1u);
        if (h1) { atomicAdd(&g_hist[b][map_f32(v1.y) >> 16], 1u);
                  atomicAdd(&g_hist[b][map_f32(v1.w) >> 16], 1u); }
        if (h2) { atomicAdd(&g_hist[b][map_f32(v2.y) >> 16], 1u);
                  atomicAdd(&g_hist[b][map_f32(v2.w) >> 16], 1u); }
        if (h3) { atomicAdd(&g_hist[b][map_f32(v3.y) >> 16], 1u);
                  atomicAdd(&g_hist[b][map_f32(v3.w) >> 16], 1u); }
    }
}

// ---------------- K2: coarse threshold ----------------
__global__ void k_thresh() {
    int b = blockIdx.x;
    __shared__ unsigned csum[256];
    unsigned s = 0;
    int c = threadIdx.x;
    for (int k = 0; k < 256; k++) s += g_hist[b][c * 256 + k];
    csum[c] = s;
    __syncthreads();
    if (threadIdx.x == 0) {
        unsigned cum = 0;
        int chunk = 255;
        while (chunk > 0 && cum + csum[chunk] < (unsigned)KPRE) { cum += csum[chunk]; chunk--; }
        int bin = chunk * 256 + 255;
        while (bin > chunk * 256 && cum + g_hist[b][bin] < (unsigned)KPRE) { cum += g_hist[b][bin]; bin--; }
        g_thresh[b] = (unsigned)bin << 16;
    }
}

// ---------------- K3: compact candidates (2-way ILP, warp-agg atomics) ----------------
__global__ void k_compact(const float4* __restrict__ scores4) {
    int b = blockIdx.y;
    unsigned th = g_thresh[b];
    const float4* sp = scores4 + (size_t)b * (NANCH / 2);
    const int M = NANCH / 2;
    int S = gridDim.x * blockDim.x;
    int tid = blockIdx.x * blockDim.x + threadIdx.x;
    int bound = ((M + 2 * S - 1) / (2 * S)) * (2 * S);
    unsigned lanebit = 1u << (threadIdx.x & 31);
    for (int i = tid; i < bound; i += 2 * S) {
        bool in0 = i < M, in1 = i + S < M;
        unsigned m0 = 0, m1 = 0, m2 = 0, m3 = 0;
        if (in0) { float4 v = sp[i];     m0 = map_f32(v.y); m1 = map_f32(v.w); }
        if (in1) { float4 v = sp[i + S]; m2 = map_f32(v.y); m3 = map_f32(v.w); }
        bool p0 = in0 && m0 >= th, p1 = in0 && m1 >= th;
        bool p2 = in1 && m2 >= th, p3 = in1 && m3 >= th;
        unsigned b0 = __ballot_sync(0xffffffffu, p0);
        unsigned b1 = __ballot_sync(0xffffffffu, p1);
        unsigned b2 = __ballot_sync(0xffffffffu, p2);
        unsigned b3 = __ballot_sync(0xffffffffu, p3);
        int c0 = __popc(b0), c1 = __popc(b1), c2 = __popc(b2), c3 = __popc(b3);
        int ctot = c0 + c1 + c2 + c3;
        if (ctot) {
            int base = 0;
            if ((threadIdx.x & 31) == 0) base = atomicAdd(&g_count[b], ctot);
            base = __shfl_sync(0xffffffffu, base, 0);
            if (p0) {
                int pos = base + __popc(b0 & (lanebit - 1));
                if (pos < CAND_CAP)
                    g_cand[b][pos] = ((u64)m0 << 32) | (u64)(0xFFFFFFFFu - (unsigned)(2 * i));
            }
            if (p1) {
                int pos = base + c0 + __popc(b1 & (lanebit - 1));
                if (pos < CAND_CAP)
                    g_cand[b][pos] = ((u64)m1 << 32) | (u64)(0xFFFFFFFFu - (unsigned)(2 * i + 1));
            }
            if (p2) {
                int pos = base + c0 + c1 + __popc(b2 & (lanebit - 1));
                if (pos < CAND_CAP)
                    g_cand[b][pos] = ((u64)m2 << 32) | (u64)(0xFFFFFFFFu - (unsigned)(2 * (i + S)));
            }
            if (p3) {
                int pos = base + c0 + c1 + c2 + __popc(b3 & (lanebit - 1));
                if (pos < CAND_CAP)
                    g_cand[b][pos] = ((u64)m3 << 32) | (u64)(0xFFFFFFFFu - (unsigned)(2 * (i + S) + 1));
            }
        }
    }
}

// ---------------- K4: refine threshold to 24 bits; compact into g_cand2 ----------------
__global__ void k_refine() {
    int b = blockIdx.x;
    __shared__ unsigned h[256];
    __shared__ unsigned above;
    __shared__ int pos;
    __shared__ unsigned s_rth;
    int cnt = g_count[b];
    if (cnt > CAND_CAP) cnt = CAND_CAP;
    unsigned cbhi = g_thresh[b];
    if (threadIdx.x < 256) h[threadIdx.x] = 0;
    if (threadIdx.x == 0) { above = 0; pos = 0; }
    __syncthreads();
    for (int i = threadIdx.x; i < cnt; i += blockDim.x) {
        unsigned m = (unsigned)(g_cand[b][i] >> 32);
        if (m >= cbhi + 0x10000u) atomicAdd(&above, 1u);
        else atomicAdd(&h[(m >> 8) & 0xFF], 1u);
    }
    __syncthreads();
    if (threadIdx.x == 0) {
        unsigned cum = above;
        int sb = 255;
        while (sb > 0 && cum + h[sb] < (unsigned)KPRE) { cum += h[sb]; sb--; }
        s_rth = cbhi + ((unsigned)sb << 8);
    }
    __syncthreads();
    for (int i = threadIdx.x; i < SORT_N; i += blockDim.x) g_cand2[b][i] = 0ull;
    __syncthreads();
    unsigned th = s_rth;
    int bound = ((cnt + blockDim.x - 1) / blockDim.x) * blockDim.x;
    unsigned lanebit = 1u << (threadIdx.x & 31);
    for (int i = threadIdx.x; i < bound; i += blockDim.x) {
        u64 key = (i < cnt) ? g_cand[b][i] : 0ull;
        bool p = (i < cnt) && ((unsigned)(key >> 32) >= th);
        unsigned bl = __ballot_sync(0xffffffffu, p);
        int base = 0;
        if (bl) {
            if ((threadIdx.x & 31) == 0) base = atomicAdd(&pos, __popc(bl));
            base = __shfl_sync(0xffffffffu, base, 0);
            if (p) {
                int o = base + __popc(bl & (lanebit - 1));
                if (o < SORT_N) g_cand2[b][o] = key;
            }
        }
    }
}

// ---------------- K5: sort 256-key chunks (descending bitonic, in smem) ----------
__global__ void k_sort256() {
    __shared__ u64 keys[CHUNK];
    int b = blockIdx.y;
    int base = blockIdx.x * CHUNK;
    int t = threadIdx.x;
    keys[t] = g_cand2[b][base + t];
    __syncthreads();
    for (int k = 2; k <= CHUNK; k <<= 1) {
        for (int j = k >> 1; j > 0; j >>= 1) {
            int ixj = t ^ j;
            if (ixj > t) {
                bool desc = ((t & k) == 0);
                u64 a = keys[t], c = keys[ixj];
                bool swap = desc ? (a < c) : (a > c);
                if (swap) { keys[t] = c; keys[ixj] = a; }
            }
            __syncthreads();
        }
    }
    g_cand2[b][base + t] = keys[t];
}

// ---------------- K6: merge-path pass (descending, stable) ----------------
// dir=0: g_cand2 -> g_cand ; dir=1: g_cand -> g_cand2
// (device globals referenced INSIDE device code — host-side &g_cand was the R4 bug)
__global__ void k_mergepass(int dir, int run) {
    int e = blockIdx.x * blockDim.x + threadIdx.x;   // 0..SORT_N-1
    int b = blockIdx.y;
    const u64* s = dir ? &g_cand[b][0] : &g_cand2[b][0];
    u64*       d = dir ? &g_cand2[b][0] : &g_cand[b][0];
    int base = e & ~(2 * run - 1);
    int local = e - base;
    u64 x = s[e];
    int pos;
    if (local < run) {
        // element of A: count of B strictly greater
        const u64* B = s + base + run;
        int lo = 0, hi = run;
        while (lo < hi) { int mid = (lo + hi) >> 1; if (B[mid] > x) lo = mid + 1; else hi = mid; }
        pos = base + local + lo;
    } else {
        // element of B: count of A greater-or-equal (stable: A wins ties)
        const u64* A = s + base;
        int j = local - run;
        int lo = 0, hi = run;
        while (lo < hi) { int mid = (lo + hi) >> 1; if (A[mid] >= x) lo = mid + 1; else hi = mid; }
        pos = base + lo + j;
    }
    d[pos] = x;
}

// ---------------- K7: decode boxes ----------------
__global__ void k_boxes(const float4* __restrict__ deltas,
                        const float4* __restrict__ anchors) {
    int b = blockIdx.y;
    int r = blockIdx.x * blockDim.x + threadIdx.x;
    if (r >= KPRE) return;
    u64 key = g_cand[b][r];
    unsigned idx = 0xFFFFFFFFu - (unsigned)(key & 0xFFFFFFFFull);
    if (idx >= NANCH) idx = 0;
    float4 an = anchors[idx];
    float4 dl = deltas[(size_t)b * NANCH + idx];
    float d0 = __fmul_rn(dl.x, 0.1f);
    float d1 = __fmul_rn(dl.y, 0.1f);
    float d2 = __fmul_rn(dl.z, 0.2f);
    float d3 = __fmul_rn(dl.w, 0.2f);
    float h = __fsub_rn(an.z, an.x);
    float w = __fsub_rn(an.w, an.y);
    float cy = __fadd_rn(__fadd_rn(an.x, __fmul_rn(0.5f, h)), __fmul_rn(d0, h));
    float cx = __fadd_rn(__fadd_rn(an.y, __fmul_rn(0.5f, w)), __fmul_rn(d1, w));
    float e2 = (float)exp((double)d2);
    float e3 = (float)exp((double)d3);
    float h2 = __fmul_rn(h, e2);
    float w2 = __fmul_rn(w, e3);
    float y1 = __fsub_rn(cy, __fmul_rn(0.5f, h2));
    float x1 = __fsub_rn(cx, __fmul_rn(0.5f, w2));
    float y2 = __fadd_rn(y1, h2);
    float x2 = __fadd_rn(x1, w2);
    y1 = fminf(fmaxf(y1, 0.f), 1.f);
    x1 = fminf(fmaxf(x1, 0.f), 1.f);
    y2 = fminf(fmaxf(y2, 0.f), 1.f);
    x2 = fminf(fmaxf(x2, 0.f), 1.f);
    g_boxes[b][r] = make_float4(y1, x1, y2, x2);
    g_areas[b][r] = __fmul_rn(__fsub_rn(y2, y1), __fsub_rn(x2, x1));
}

// ---------------- K8: spatial counting sort by Morton(center) + tile AABBs ----
__global__ void k_spatial() {
    int b = blockIdx.x;
    __shared__ int hist[256];
    __shared__ int offs[256];
    __shared__ unsigned char mcell[KPRE];
    int t = threadIdx.x;
    if (t < 256) hist[t] = 0;
    __syncthreads();
    for (int r = t; r < KPRE; r += blockDim.x) {
        float4 bx = g_boxes[b][r];
        float cy = 0.5f * (bx.x + bx.z);
        float cx = 0.5f * (bx.y + bx.w);
        int iy = (int)(cy * 16.f); iy = iy < 0 ? 0 : (iy > 15 ? 15 : iy);
        int ix = (int)(cx * 16.f); ix = ix < 0 ? 0 : (ix > 15 ? 15 : ix);
        int m = 0;
        #pragma unroll
        for (int k = 0; k < 4; k++)
            m |= (((iy >> k) & 1) << (2 * k + 1)) | (((ix >> k) & 1) << (2 * k));
        mcell[r] = (unsigned char)m;
        atomicAdd(&hist[m], 1);
    }
    __syncthreads();
    if (t == 0) {
        int run = 0;
        for (int k = 0; k < 256; k++) { offs[k] = run; run += hist[k]; }
    }
    __syncthreads();
    for (int r = t; r < KPRE; r += blockDim.x) {
        int m = mcell[r];
        int pos = atomicAdd(&offs[m], 1);
        g_sbox[b][pos] = g_boxes[b][r];
        g_sarea[b][pos] = g_areas[b][r];
        g_srank[b][pos] = r;
    }
    if (t < NSLOT - KPRE) {
        int pos = KPRE + t;
        g_sbox[b][pos] = make_float4(9e9f, 9e9f, -9e9f, -9e9f);
        g_sarea[b][pos] = 0.f;
        g_srank[b][pos] = 0x7FFFFFFF;
    }
    __syncthreads();
    if (t < TILES) {
        float miny = 9e9f, minx = 9e9f, maxy = -9e9f, maxx = -9e9f;
        for (int e = 0; e < 64; e++) {
            int s = t * 64 + e;
            if (g_srank[b][s] >= KPRE) continue;
            float4 bx = g_sbox[b][s];
            miny = fminf(miny, bx.x); minx = fminf(minx, bx.y);
            maxy = fmaxf(maxy, bx.z); maxx = fmaxf(maxx, bx.w);
        }
        g_aabb[b][t] = make_float4(miny, minx, maxy, maxx);
    }
}

// ---------------- K9: pair kernel — culled tiles, sparse atomic mask ----------------
__global__ void k_pairs() {
    int tA = blockIdx.x, tB = blockIdx.y, b = blockIdx.z;
    if (tB < tA) return;
    float4 aA = g_aabb[b][tA];
    float4 aB = g_aabb[b][tB];
    if (!(aA.z > aB.x && aB.z > aA.x && aA.w > aB.y && aB.w > aA.y)) return;

    __shared__ float4 sb4[64];
    __shared__ float  sar[64];
    __shared__ int    srk[64];
    int t = threadIdx.x;
    int row = t & 63;
    int half = t >> 6;
    if (t < 64) {
        int s = tB * 64 + t;
        sb4[t] = g_sbox[b][s];
        sar[t] = g_sarea[b][s];
        srk[t] = g_srank[b][s];
    }
    __syncthreads();

    int sa = tA * 64 + row;
    int ra = g_srank[b][sa];
    if (ra >= KPRE) return;
    float4 bi = g_sbox[b][sa];
    float  ai = g_sarea[b][sa];
    if (!(bi.z > aB.x && aB.z > bi.x && bi.w > aB.y && aB.w > bi.y)) return;

    int j0 = half * 32;
    #pragma unroll 4
    for (int jj = j0; jj < j0 + 32; ++jj) {
        if (tA == tB && jj <= row) continue;
        int rb = srk[jj];
        if (rb >= KPRE) continue;
        float4 bj = sb4[jj];
        float yy1 = fmaxf(bi.x, bj.x);
        float xx1 = fmaxf(bi.y, bj.y);
        float yy2 = fminf(bi.z, bj.z);
        float xx2 = fminf(bi.w, bj.w);
        float dh = __fsub_rn(yy2, yy1);
        float dw = __fsub_rn(xx2, xx1);
        if (dh > 0.f && dw > 0.f) {
            float inter = __fmul_rn(dh, dw);
            float u = __fsub_rn(__fadd_rn(ai, sar[jj]), inter);
            if (u > 0.f) {
                bool sup;
                if (inter > __fmul_rn(0.71f, u)) sup = true;
                else if (inter >= __fmul_rn(0.69f, u)) sup = __fdiv_rn(inter, u) > 0.7f;
                else sup = false;
                if (sup) {
                    int rmin = ra < rb ? ra : rb;
                    int rmax = ra < rb ? rb : ra;
                    atomicOr(&g_mask[b][rmin][rmax >> 6], 1ull << (rmax & 63));
                    atomicOr(&g_rowbits[b][rmin >> 6], 1ull << (rmin & 63));
                }
            }
        }
    }
}

// ---------------- K10: greedy reduce (1 warp per batch), rowbits shortcut ----------
__global__ void k_reduce(float* __restrict__ out) {
    int b = blockIdx.x;
    int lane = threadIdx.x;
    __shared__ int sel[KOUT];
    u64 rm0 = 0ull, rm1 = 0ull, rm2 = 0ull;
    const u64* mask = &g_mask[b][0][0];
    u64 hb0 = g_rowbits[b][lane];
    u64 hb1 = g_rowbits[b][lane + 32];
    u64 hb2 = (lane + 64 < WORDS) ? g_rowbits[b][lane + 64] : 0ull;
    int cnt = 0;

    for (int w = 0; w < WORDS && cnt < KOUT; ++w) {
        int slot = w >> 5;
        int owner = w & 31;
        u64 rmv = (slot == 0) ? rm0 : ((slot == 1) ? rm1 : rm2);
        u64 hbv = (slot == 0) ? hb0 : ((slot == 1) ? hb1 : hb2);
        u64 cur = __shfl_sync(0xffffffffu, rmv, owner);
        u64 hasw = __shfl_sync(0xffffffffu, hbv, owner);
        u64 wm = (w == WORDS - 1) ? ((1ull << 48) - 1) : ~0ull;
        u64 valid = ~cur & wm;

        while (valid) {
            int bpos = __ffsll((long long)valid) - 1;
            int i = (w << 6) + bpos;
            if (lane == 0) sel[cnt] = i;
            cnt++;
            if (cnt >= KOUT) break;
            if ((hasw >> bpos) & 1ull) {
                const u64* rowp = mask + (size_t)i * WSTRIDE;
                u64 r0 = __ldg(rowp + lane);
                u64 r1 = __ldg(rowp + lane + 32);
                u64 r2 = (lane + 64 < WORDS) ? __ldg(rowp + lane + 64) : 0ull;
                rm0 |= r0;
                rm1 |= r1;
                rm2 |= r2;
                u64 rw = (slot == 0) ? r0 : ((slot == 1) ? r1 : r2);
                cur |= __shfl_sync(0xffffffffu, rw, owner);
            }
            u64 above = (bpos == 63) ? 0ull : (~0ull << (bpos + 1));
            valid = ~cur & wm & above;
        }
    }
    __syncwarp();

    float4* o = (float4*)(out + (size_t)b * KOUT * 4);
    for (int r = lane; r < KOUT; r += 32) {
        float4 v = make_float4(0.f, 0.f, 0.f, 0.f);
        if (r < cnt) v = g_boxes[b][sel[r]];
        o[r] = v;
    }
}

// ---------------- launch ----------------
extern "C" void kernel_launch(void* const* d_in, const int* in_sizes, int n_in,
                              void* d_out, int out_size) {
    const float4* scores4 = (const float4*)d_in[0];
    const float4* deltas  = (const float4*)d_in[1];
    const float4* anchors = (const float4*)d_in[2];
    float* out = (float*)d_out;

    k_zero<<<1024, 1024>>>();
    {
        dim3 g(128, BATCH);
        k_hist<<<g, 256>>>(scores4);
    }
    k_thresh<<<BATCH, 256>>>();
    {
        dim3 g(128, BATCH);
        k_compact<<<g, 256>>>(scores4);
    }
    k_refine<<<BATCH, 256>>>();
    {
        dim3 g(NCHUNK, BATCH);
        k_sort256<<<g, CHUNK>>>();
    }
    {
        dim3 g(SORT_N / 256, BATCH);
        k_mergepass<<<g, 256>>>(0, 256);    // g_cand2 -> g_cand
        k_mergepass<<<g, 256>>>(1, 512);    // g_cand  -> g_cand2
        k_mergepass<<<g, 256>>>(0, 1024);   // g_cand2 -> g_cand
        k_mergepass<<<g, 256>>>(1, 2048);   // g_cand  -> g_cand2
        k_mergepass<<<g, 256>>>(0, 4096);   // g_cand2 -> g_cand (final)
    }
    {
        dim3 g((KPRE + 255) / 256, BATCH);
        k_boxes<<<g, 256>>>(deltas, anchors);
    }
    k_spatial<<<BATCH, 256>>>();
    {
        dim3 g(TILES, TILES, BATCH);
        k_pairs<<<g, 128>>>();
    }
    k_reduce<<<BATCH, 32>>>(out);
}

// round 6
// speedup vs baseline: 3.0548x; 1.5134x over previous
#include <cuda_runtime.h>
#include <cstdint>
#include <math.h>

#define BATCH     8
#define NANCH     1047552
#define KPRE      6000
#define KOUT      1000
#define CAND_CAP  16384
#define SORT_N    16384
#define CHUNK     256
#define NCHUNK    (SORT_N / CHUNK)
#define WORDS     94          /* ceil(6000/64) */
#define WSTRIDE   96          /* padded row stride (768B, 128B-aligned) */
#define NBINS     65536
#define TILES     94
#define NSLOT     (TILES*64)  /* 6016 */
#define LRANK     2560        /* head/tail split (40 tiles) */
#define HTILES    40
#define TTILES    54

typedef unsigned long long u64;

// ---------------- device scratch (static, no allocations) ----------------
__device__ __align__(128) unsigned int g_hist[BATCH][NBINS];
__device__ __align__(128) unsigned int g_thresh[BATCH];
__device__ __align__(128) int          g_count[BATCH];
__device__ int g_flagA;   // candidate-extraction fallback needed
__device__ int g_flagB;   // tail-pairs fallback needed
__device__ __align__(128) u64          g_cand[BATCH][CAND_CAP];
__device__ __align__(128) u64          g_cand2[BATCH][SORT_N];
__device__ __align__(128) float4       g_boxes[BATCH][KPRE];
__device__ __align__(128) float        g_areas[BATCH][KPRE];
__device__ __align__(128) u64          g_mask[BATCH][KPRE][WSTRIDE];
__device__ __align__(128) u64          g_rowbits[BATCH][WSTRIDE];
__device__ __align__(128) float4       g_sbox[BATCH][NSLOT];
__device__ __align__(128) float        g_sarea[BATCH][NSLOT];
__device__ __align__(128) int          g_srank[BATCH][NSLOT];
__device__ __align__(128) float4       g_aabb[BATCH][TILES];

__device__ __forceinline__ unsigned map_f32(float v) {
    unsigned b = __float_as_uint(v);
    return b ^ ((b & 0x80000000u) ? 0xFFFFFFFFu : 0x80000000u);
}

// ---------------- K0: zero counts/flags/rowbits/mask(head rows)/cand ----------------
__global__ void k_zero() {
    int idx = blockIdx.x * blockDim.x + threadIdx.x;
    int stride = gridDim.x * blockDim.x;
    if (idx < BATCH) g_count[idx] = 0;
    if (idx == 0) { g_flagA = 0; g_flagB = 0; }
    u64* rb = &g_rowbits[0][0];
    const int rtot = BATCH * WSTRIDE;
    for (int i = idx; i < rtot; i += stride) rb[i] = 0ull;
    // mask rows < LRANK only
    for (int i = idx; i < BATCH * LRANK * WSTRIDE; i += stride) {
        int b = i / (LRANK * WSTRIDE);
        int rem = i - b * (LRANK * WSTRIDE);
        g_mask[b][rem / WSTRIDE][rem % WSTRIDE] = 0ull;
    }
    u64* c = &g_cand[0][0];
    for (int i = idx; i < BATCH * CAND_CAP; i += stride) c[i] = 0ull;
}

// ---------------- K1: static-threshold compact (2-way ILP, warp-agg atomics) -------
__global__ void k_compactS(const float4* __restrict__ scores4) {
    int b = blockIdx.y;
    const unsigned th = map_f32(0.99f);   // static pre-threshold (uniform scores)
    const float4* sp = scores4 + (size_t)b * (NANCH / 2);
    const int M = NANCH / 2;
    int S = gridDim.x * blockDim.x;
    int tid = blockIdx.x * blockDim.x + threadIdx.x;
    int bound = ((M + 2 * S - 1) / (2 * S)) * (2 * S);
    unsigned lanebit = 1u << (threadIdx.x & 31);
    for (int i = tid; i < bound; i += 2 * S) {
        bool in0 = i < M, in1 = i + S < M;
        unsigned m0 = 0, m1 = 0, m2 = 0, m3 = 0;
        if (in0) { float4 v = sp[i];     m0 = map_f32(v.y); m1 = map_f32(v.w); }
        if (in1) { float4 v = sp[i + S]; m2 = map_f32(v.y); m3 = map_f32(v.w); }
        bool p0 = in0 && m0 >= th, p1 = in0 && m1 >= th;
        bool p2 = in1 && m2 >= th, p3 = in1 && m3 >= th;
        unsigned b0 = __ballot_sync(0xffffffffu, p0);
        unsigned b1 = __ballot_sync(0xffffffffu, p1);
        unsigned b2 = __ballot_sync(0xffffffffu, p2);
        unsigned b3 = __ballot_sync(0xffffffffu, p3);
        int c0 = __popc(b0), c1 = __popc(b1), c2 = __popc(b2), c3 = __popc(b3);
        int ctot = c0 + c1 + c2 + c3;
        if (ctot) {
            int base = 0;
            if ((threadIdx.x & 31) == 0) base = atomicAdd(&g_count[b], ctot);
            base = __shfl_sync(0xffffffffu, base, 0);
            if (p0) { int pos = base + __popc(b0 & (lanebit - 1));
                if (pos < CAND_CAP) g_cand[b][pos] = ((u64)m0 << 32) | (u64)(0xFFFFFFFFu - (unsigned)(2 * i)); }
            if (p1) { int pos = base + c0 + __popc(b1 & (lanebit - 1));
                if (pos < CAND_CAP) g_cand[b][pos] = ((u64)m1 << 32) | (u64)(0xFFFFFFFFu - (unsigned)(2 * i + 1)); }
            if (p2) { int pos = base + c0 + c1 + __popc(b2 & (lanebit - 1));
                if (pos < CAND_CAP) g_cand[b][pos] = ((u64)m2 << 32) | (u64)(0xFFFFFFFFu - (unsigned)(2 * (i + S))); }
            if (p3) { int pos = base + c0 + c1 + c2 + __popc(b3 & (lanebit - 1));
                if (pos < CAND_CAP) g_cand[b][pos] = ((u64)m3 << 32) | (u64)(0xFFFFFFFFu - (unsigned)(2 * (i + S) + 1)); }
        }
    }
}

// ---------------- K2: verify candidate counts; arm fallback ----------------
__global__ void k_check() {
    int t = threadIdx.x;
    __shared__ int bad;
    if (t == 0) bad = 0;
    __syncthreads();
    if (t < BATCH) {
        int c = g_count[t];
        if (c < KPRE || c > CAND_CAP) atomicExch(&bad, 1);
    }
    __syncthreads();
    if (t == 0) g_flagA = bad;
    __syncthreads();
    if (bad && t < BATCH) g_count[t] = 0;
}

// ---------------- gated fallback: zero hist + cand ----------------
__global__ void k_zeroF() {
    if (!g_flagA) return;
    int idx = blockIdx.x * blockDim.x + threadIdx.x;
    int stride = gridDim.x * blockDim.x;
    unsigned* h = &g_hist[0][0];
    for (int i = idx; i < BATCH * NBINS; i += stride) h[i] = 0u;
    u64* c = &g_cand[0][0];
    for (int i = idx; i < BATCH * CAND_CAP; i += stride) c[i] = 0ull;
}

// ---------------- gated fallback: histogram ----------------
__global__ void k_histF(const float4* __restrict__ scores4) {
    if (!g_flagA) return;
    int b = blockIdx.y;
    const float4* sp = scores4 + (size_t)b * (NANCH / 2);
    const int M = NANCH / 2;
    int S = gridDim.x * blockDim.x;
    for (int i = blockIdx.x * blockDim.x + threadIdx.x; i < M; i += S) {
        float4 v = sp[i];
        atomicAdd(&g_hist[b][map_f32(v.y) >> 16], 1u);
        atomicAdd(&g_hist[b][map_f32(v.w) >> 16], 1u);
    }
}

// ---------------- gated fallback: coarse threshold ----------------
__global__ void k_threshF() {
    if (!g_flagA) return;
    int b = blockIdx.x;
    __shared__ unsigned csum[256];
    unsigned s = 0;
    int c = threadIdx.x;
    for (int k = 0; k < 256; k++) s += g_hist[b][c * 256 + k];
    csum[c] = s;
    __syncthreads();
    if (threadIdx.x == 0) {
        unsigned cum = 0;
        int chunk = 255;
        while (chunk > 0 && cum + csum[chunk] < (unsigned)KPRE) { cum += csum[chunk]; chunk--; }
        int bin = chunk * 256 + 255;
        while (bin > chunk * 256 && cum + g_hist[b][bin] < (unsigned)KPRE) { cum += g_hist[b][bin]; bin--; }
        g_thresh[b] = (unsigned)bin << 16;
    }
}

// ---------------- gated fallback: compact with data-derived threshold ----------------
__global__ void k_compactF(const float4* __restrict__ scores4) {
    if (!g_flagA) return;
    int b = blockIdx.y;
    unsigned th = g_thresh[b];
    const float4* sp = scores4 + (size_t)b * (NANCH / 2);
    const int M = NANCH / 2;
    int S = gridDim.x * blockDim.x;
    int tid = blockIdx.x * blockDim.x + threadIdx.x;
    int bound = ((M + S - 1) / S) * S;
    unsigned lanebit = 1u << (threadIdx.x & 31);
    for (int i = tid; i < bound; i += S) {
        bool in = i < M;
        unsigned m0 = 0, m1 = 0;
        if (in) { float4 v = sp[i]; m0 = map_f32(v.y); m1 = map_f32(v.w); }
        bool p0 = in && m0 >= th, p1 = in && m1 >= th;
        unsigned b0 = __ballot_sync(0xffffffffu, p0);
        unsigned b1 = __ballot_sync(0xffffffffu, p1);
        int c0 = __popc(b0), c1 = __popc(b1);
        if (c0 + c1) {
            int base = 0;
            if ((threadIdx.x & 31) == 0) base = atomicAdd(&g_count[b], c0 + c1);
            base = __shfl_sync(0xffffffffu, base, 0);
            if (p0) { int pos = base + __popc(b0 & (lanebit - 1));
                if (pos < CAND_CAP) g_cand[b][pos] = ((u64)m0 << 32) | (u64)(0xFFFFFFFFu - (unsigned)(2 * i)); }
            if (p1) { int pos = base + c0 + __popc(b1 & (lanebit - 1));
                if (pos < CAND_CAP) g_cand[b][pos] = ((u64)m1 << 32) | (u64)(0xFFFFFFFFu - (unsigned)(2 * i + 1)); }
        }
    }
}

// ---------------- K5: sort 256-key chunks in g_cand (descending bitonic) ----------
__global__ void k_sort256() {
    __shared__ u64 keys[CHUNK];
    int b = blockIdx.y;
    int base = blockIdx.x * CHUNK;
    int t = threadIdx.x;
    keys[t] = g_cand[b][base + t];
    __syncthreads();
    for (int k = 2; k <= CHUNK; k <<= 1) {
        for (int j = k >> 1; j > 0; j >>= 1) {
            int ixj = t ^ j;
            if (ixj > t) {
                bool desc = ((t & k) == 0);
                u64 a = keys[t], c = keys[ixj];
                bool swap = desc ? (a < c) : (a > c);
                if (swap) { keys[t] = c; keys[ixj] = a; }
            }
            __syncthreads();
        }
    }
    g_cand[b][base + t] = keys[t];
}

// ---------------- K6: merge-path pass (descending, stable) ----------------
// dir=1: g_cand -> g_cand2 ; dir=0: g_cand2 -> g_cand
__global__ void k_mergepass(int dir, int run) {
    int e = blockIdx.x * blockDim.x + threadIdx.x;
    int b = blockIdx.y;
    const u64* s = dir ? &g_cand[b][0] : &g_cand2[b][0];
    u64*       d = dir ? &g_cand2[b][0] : &g_cand[b][0];
    int base = e & ~(2 * run - 1);
    int local = e - base;
    u64 x = s[e];
    int pos;
    if (local < run) {
        const u64* B = s + base + run;
        int lo = 0, hi = run;
        while (lo < hi) { int mid = (lo + hi) >> 1; if (B[mid] > x) lo = mid + 1; else hi = mid; }
        pos = base + local + lo;
    } else {
        const u64* A = s + base;
        int j = local - run;
        int lo = 0, hi = run;
        while (lo < hi) { int mid = (lo + hi) >> 1; if (A[mid] >= x) lo = mid + 1; else hi = mid; }
        pos = base + lo + j;
    }
    d[pos] = x;
}

// ---------------- K7: decode boxes ----------------
__global__ void k_boxes(const float4* __restrict__ deltas,
                        const float4* __restrict__ anchors) {
    int b = blockIdx.y;
    int r = blockIdx.x * blockDim.x + threadIdx.x;
    if (r >= KPRE) return;
    u64 key = g_cand[b][r];
    unsigned idx = 0xFFFFFFFFu - (unsigned)(key & 0xFFFFFFFFull);
    if (idx >= NANCH) idx = 0;
    float4 an = anchors[idx];
    float4 dl = deltas[(size_t)b * NANCH + idx];
    float d0 = __fmul_rn(dl.x, 0.1f);
    float d1 = __fmul_rn(dl.y, 0.1f);
    float d2 = __fmul_rn(dl.z, 0.2f);
    float d3 = __fmul_rn(dl.w, 0.2f);
    float h = __fsub_rn(an.z, an.x);
    float w = __fsub_rn(an.w, an.y);
    float cy = __fadd_rn(__fadd_rn(an.x, __fmul_rn(0.5f, h)), __fmul_rn(d0, h));
    float cx = __fadd_rn(__fadd_rn(an.y, __fmul_rn(0.5f, w)), __fmul_rn(d1, w));
    float e2 = (float)exp((double)d2);
    float e3 = (float)exp((double)d3);
    float h2 = __fmul_rn(h, e2);
    float w2 = __fmul_rn(w, e3);
    float y1 = __fsub_rn(cy, __fmul_rn(0.5f, h2));
    float x1 = __fsub_rn(cx, __fmul_rn(0.5f, w2));
    float y2 = __fadd_rn(y1, h2);
    float x2 = __fadd_rn(x1, w2);
    y1 = fminf(fmaxf(y1, 0.f), 1.f);
    x1 = fminf(fmaxf(x1, 0.f), 1.f);
    y2 = fminf(fmaxf(y2, 0.f), 1.f);
    x2 = fminf(fmaxf(x2, 0.f), 1.f);
    g_boxes[b][r] = make_float4(y1, x1, y2, x2);
    g_areas[b][r] = __fmul_rn(__fsub_rn(y2, y1), __fsub_rn(x2, x1));
}

// ---------------- K8: head/tail spatial counting sort + tile AABBs ----------------
__global__ void k_spatial() {
    int b = blockIdx.x;
    __shared__ int hist[512];
    __shared__ int offs[512];
    __shared__ unsigned short mcell[KPRE];
    int t = threadIdx.x;
    for (int k = t; k < 512; k += blockDim.x) hist[k] = 0;
    __syncthreads();
    for (int r = t; r < KPRE; r += blockDim.x) {
        float4 bx = g_boxes[b][r];
        float cy = 0.5f * (bx.x + bx.z);
        float cx = 0.5f * (bx.y + bx.w);
        int iy = (int)(cy * 16.f); iy = iy < 0 ? 0 : (iy > 15 ? 15 : iy);
        int ix = (int)(cx * 16.f); ix = ix < 0 ? 0 : (ix > 15 ? 15 : ix);
        int m = 0;
        #pragma unroll
        for (int k = 0; k < 4; k++)
            m |= (((iy >> k) & 1) << (2 * k + 1)) | (((ix >> k) & 1) << (2 * k));
        int key = ((r < LRANK) ? 0 : 256) + m;   // head region first
        mcell[r] = (unsigned short)key;
        atomicAdd(&hist[key], 1);
    }
    __syncthreads();
    if (t == 0) {
        int run = 0;
        for (int k = 0; k < 512; k++) { offs[k] = run; run += hist[k]; }
    }
    __syncthreads();
    for (int r = t; r < KPRE; r += blockDim.x) {
        int key = mcell[r];
        int pos = atomicAdd(&offs[key], 1);
        g_sbox[b][pos] = g_boxes[b][r];
        g_sarea[b][pos] = g_areas[b][r];
        g_srank[b][pos] = r;
    }
    if (t < NSLOT - KPRE) {
        int pos = KPRE + t;
        g_sbox[b][pos] = make_float4(9e9f, 9e9f, -9e9f, -9e9f);  // AABB-neutral, never overlaps
        g_sarea[b][pos] = 0.f;
        g_srank[b][pos] = 0;
    }
    __syncthreads();
    if (t < TILES) {
        float miny = 9e9f, minx = 9e9f, maxy = -9e9f, maxx = -9e9f;
        #pragma unroll 4
        for (int e = 0; e < 64; e++) {
            float4 bx = g_sbox[b][t * 64 + e];
            miny = fminf(miny, bx.x); minx = fminf(minx, bx.y);
            maxy = fmaxf(maxy, bx.z); maxx = fmaxf(maxx, bx.w);
        }
        g_aabb[b][t] = make_float4(miny, minx, maxy, maxx);
    }
}

// ---------------- shared pair-tile body ----------------
__device__ __forceinline__ void pair_tiles(int b, int ta, int tb) {
    float4 aA = g_aabb[b][ta];
    float4 aB = g_aabb[b][tb];
    if (!(aA.z > aB.x && aB.z > aA.x && aA.w > aB.y && aB.w > aA.y)) return;
    __shared__ float4 sb4[64];
    __shared__ float  sar[64];
    __shared__ int    srk[64];
    int t = threadIdx.x;
    int row = t & 63;
    int half = t >> 6;
    if (t < 64) {
        int s = tb * 64 + t;
        sb4[t] = g_sbox[b][s];
        sar[t] = g_sarea[b][s];
        srk[t] = g_srank[b][s];
    }
    __syncthreads();
    int sa = ta * 64 + row;
    float4 bi = g_sbox[b][sa];
    float  ai = g_sarea[b][sa];
    int ra = g_srank[b][sa];
    if (!(bi.z > aB.x && aB.z > bi.x && bi.w > aB.y && aB.w > bi.y)) return;
    bool diag = (ta == tb);
    int j0 = half * 32;
    #pragma unroll 4
    for (int jj = j0; jj < j0 + 32; ++jj) {
        if (diag && jj <= row) continue;
        float4 bj = sb4[jj];
        float yy1 = fmaxf(bi.x, bj.x);
        float xx1 = fmaxf(bi.y, bj.y);
        float yy2 = fminf(bi.z, bj.z);
        float xx2 = fminf(bi.w, bj.w);
        float dh = __fsub_rn(yy2, yy1);
        float dw = __fsub_rn(xx2, xx1);
        if (dh > 0.f && dw > 0.f) {
            float inter = __fmul_rn(dh, dw);
            float u = __fsub_rn(__fadd_rn(ai, sar[jj]), inter);
            if (u > 0.f) {
                bool sup;
                if (inter > __fmul_rn(0.71f, u)) sup = true;
                else if (inter >= __fmul_rn(0.69f, u)) sup = __fdiv_rn(inter, u) > 0.7f;
                else sup = false;
                if (sup) {
                    int rb = srk[jj];
                    int rmin = ra < rb ? ra : rb;
                    int rmax = ra < rb ? rb : ra;
                    atomicOr(&g_mask[b][rmin][rmax >> 6], 1ull << (rmax & 63));
                    atomicOr(&g_rowbits[b][rmin >> 6], 1ull << (rmin & 63));
                }
            }
        }
    }
}

// ---------------- K9: pairs with at least one head tile ----------------
__global__ void k_pairs() {
    int ta = blockIdx.x;       // any tile 0..93
    int hb = blockIdx.y;       // head tile 0..39
    if (ta < hb) return;
    pair_tiles(blockIdx.z, ta, hb);
}

// ---------------- gated: zero tail mask rows ----------------
__global__ void k_zeroTailF() {
    if (!g_flagB) return;
    int idx = blockIdx.x * blockDim.x + threadIdx.x;
    int stride = gridDim.x * blockDim.x;
    const int n = BATCH * (KPRE - LRANK) * WSTRIDE;
    for (int i = idx; i < n; i += stride) {
        int b = i / ((KPRE - LRANK) * WSTRIDE);
        int rem = i - b * ((KPRE - LRANK) * WSTRIDE);
        g_mask[b][LRANK + rem / WSTRIDE][rem % WSTRIDE] = 0ull;
    }
}

// ---------------- gated: tail x tail pairs ----------------
__global__ void k_pairsTailF() {
    if (!g_flagB) return;
    int ta = HTILES + blockIdx.x;   // 40..93
    int tb = HTILES + blockIdx.y;
    if (ta < tb) return;
    pair_tiles(blockIdx.z, ta, tb);
}

// ---------------- K10: greedy reduce (1 warp per batch), rowbits + prefetch --------
// mode 0: primary (sets g_flagB on selection >= LRANK); mode 1: gated full redo
__global__ void k_reduce(float* __restrict__ out, int mode) {
    if (mode == 1 && !g_flagB) return;
    int b = blockIdx.x;
    int lane = threadIdx.x;
    __shared__ int sel[KOUT];
    u64 rm0 = 0ull, rm1 = 0ull, rm2 = 0ull;
    const u64* mask = &g_mask[b][0][0];
    u64 hb0 = g_rowbits[b][lane];
    u64 hb1 = g_rowbits[b][lane + 32];
    u64 hb2 = (lane + 64 < WORDS) ? g_rowbits[b][lane + 64] : 0ull;
    int cnt = 0;

    for (int w = 0; w < WORDS && cnt < KOUT; ++w) {
        int slot = w >> 5;
        int owner = w & 31;
        u64 rmv = (slot == 0) ? rm0 : ((slot == 1) ? rm1 : rm2);
        u64 hbv = (slot == 0) ? hb0 : ((slot == 1) ? hb1 : hb2);
        u64 cur = __shfl_sync(0xffffffffu, rmv, owner);
        u64 hasw = __shfl_sync(0xffffffffu, hbv, owner);
        u64 wm = (w == WORDS - 1) ? ((1ull << 48) - 1) : ~0ull;
        u64 valid = ~cur & wm;

        // prefetch rows of next suppressor candidates in this word
        {
            u64 pf = valid & hasw;
            #pragma unroll
            for (int c = 0; c < 2; c++) {
                if (!pf) break;
                int nb = __ffsll((long long)pf) - 1;
                pf &= pf - 1;
                const char* p = (const char*)(mask + (size_t)((w << 6) + nb) * WSTRIDE);
                if ((lane >> 3) == c && (lane & 7) < 6)
                    asm volatile("prefetch.global.L1 [%0];" :: "l"(p + (lane & 7) * 128));
            }
        }

        while (valid) {
            int bpos = __ffsll((long long)valid) - 1;
            int i = (w << 6) + bpos;
            if (lane == 0) {
                sel[cnt] = i;
                if (mode == 0 && i >= LRANK) g_flagB = 1;
            }
            cnt++;
            if (cnt >= KOUT) break;
            if ((hasw >> bpos) & 1ull) {
                const u64* rowp = mask + (size_t)i * WSTRIDE;
                u64 r0 = __ldg(rowp + lane);
                u64 r1 = __ldg(rowp + lane + 32);
                u64 r2 = (lane + 64 < WORDS) ? __ldg(rowp + lane + 64) : 0ull;
                rm0 |= r0;
                rm1 |= r1;
                rm2 |= r2;
                u64 rw = (slot == 0) ? r0 : ((slot == 1) ? r1 : r2);
                cur |= __shfl_sync(0xffffffffu, rw, owner);
                u64 above = (bpos == 63) ? 0ull : (~0ull << (bpos + 1));
                valid = ~cur & wm & above;
                // refresh prefetch after suppression changed the candidate set
                u64 pf = valid & hasw;
                #pragma unroll
                for (int c = 0; c < 2; c++) {
                    if (!pf) break;
                    int nb = __ffsll((long long)pf) - 1;
                    pf &= pf - 1;
                    const char* p = (const char*)(mask + (size_t)((w << 6) + nb) * WSTRIDE);
                    if ((lane >> 3) == c && (lane & 7) < 6)
                        asm volatile("prefetch.global.L1 [%0];" :: "l"(p + (lane & 7) * 128));
                }
            } else {
                u64 above = (bpos == 63) ? 0ull : (~0ull << (bpos + 1));
                valid &= above;
            }
        }
    }
    __syncwarp();

    float4* o = (float4*)(out + (size_t)b * KOUT * 4);
    for (int r = lane; r < KOUT; r += 32) {
        float4 v = make_float4(0.f, 0.f, 0.f, 0.f);
        if (r < cnt) v = g_boxes[b][sel[r]];
        o[r] = v;
    }
}

// ---------------- launch ----------------
extern "C" void kernel_launch(void* const* d_in, const int* in_sizes, int n_in,
                              void* d_out, int out_size) {
    const float4* scores4 = (const float4*)d_in[0];
    const float4* deltas  = (const float4*)d_in[1];
    const float4* anchors = (const float4*)d_in[2];
    float* out = (float*)d_out;

    k_zero<<<512, 1024>>>();
    {
        dim3 g(128, BATCH);
        k_compactS<<<g, 256>>>(scores4);
    }
    k_check<<<1, 32>>>();
    // gated fallback chain (no-ops when flagA == 0)
    k_zeroF<<<128, 1024>>>();
    {
        dim3 g(128, BATCH);
        k_histF<<<g, 256>>>(scores4);
    }
    k_threshF<<<BATCH, 256>>>();
    {
        dim3 g(128, BATCH);
        k_compactF<<<g, 256>>>(scores4);
    }
    // sort 16384 keys: 64 chunk sorts + 6 merge passes (ends in g_cand)
    {
        dim3 g(NCHUNK, BATCH);
        k_sort256<<<g, CHUNK>>>();
    }
    {
        dim3 g(SORT_N / 256, BATCH);
        k_mergepass<<<g, 256>>>(1, 256);
        k_mergepass<<<g, 256>>>(0, 512);
        k_mergepass<<<g, 256>>>(1, 1024);
        k_mergepass<<<g, 256>>>(0, 2048);
        k_mergepass<<<g, 256>>>(1, 4096);
        k_mergepass<<<g, 256>>>(0, 8192);
    }
    {
        dim3 g((KPRE + 255) / 256, BATCH);
        k_boxes<<<g, 256>>>(deltas, anchors);
    }
    k_spatial<<<BATCH, 256>>>();
    {
        dim3 g(TILES, HTILES, BATCH);
        k_pairs<<<g, 128>>>();
    }
    k_reduce<<<BATCH, 32>>>(out, 0);
    // gated tail fallback (no-ops when flagB == 0)
    k_zeroTailF<<<256, 1024>>>();
    {
        dim3 g(TTILES, TTILES, BATCH);
        k_pairsTailF<<<g, 128>>>();
    }
    k_reduce<<<BATCH, 32>>>(out, 1);
}

// round 7
// speedup vs baseline: 3.0584x; 1.0012x over previous
#include <cuda_runtime.h>
#include <cstdint>
#include <math.h>

#define BATCH     8
#define NANCH     1047552
#define KPRE      6000
#define KOUT      1000
#define CAND_CAP  16384
#define SORT_N    8192
#define CHUNK     256
#define NCHUNK    (SORT_N / CHUNK)
#define WORDS     94
#define WSTRIDE   96
#define NBINS     65536
#define TILES     94
#define NSLOT     (TILES*64)
#define LRANK     2560
#define HTILES    40
#define TTILES    54

typedef unsigned long long u64;

// ---------------- device scratch ----------------
__device__ __align__(128) unsigned int g_hist[BATCH][NBINS];
__device__ __align__(128) unsigned int g_thresh[BATCH];
__device__ __align__(128) int          g_count[BATCH];
__device__ int g_flagA;
__device__ int g_flagB;
__device__ __align__(128) u64          g_cand[BATCH][CAND_CAP];
__device__ __align__(128) u64          g_cand2[BATCH][SORT_N];
__device__ __align__(128) float4       g_boxes[BATCH][KPRE];
__device__ __align__(128) float        g_areas[BATCH][KPRE];
__device__ __align__(128) u64          g_mask[BATCH][KPRE][WSTRIDE];
__device__ __align__(128) u64          g_rowbits[BATCH][WSTRIDE];
__device__ __align__(128) float4       g_sbox[BATCH][NSLOT];
__device__ __align__(128) float        g_sarea[BATCH][NSLOT];
__device__ __align__(128) int          g_srank[BATCH][NSLOT];
__device__ __align__(128) float4       g_aabb[BATCH][TILES];

__device__ __forceinline__ unsigned map_f32(float v) {
    unsigned b = __float_as_uint(v);
    return b ^ ((b & 0x80000000u) ? 0xFFFFFFFFu : 0x80000000u);
}

// ============ double-float (df64) exp: f32-only, ~2^-40 relative accuracy ============
struct df { float h, l; };
__device__ __forceinline__ df df_two_sum(float a, float b) {
    float s = __fadd_rn(a, b);
    float v = __fsub_rn(s, a);
    float e = __fadd_rn(__fsub_rn(a, __fsub_rn(s, v)), __fsub_rn(b, v));
    df r; r.h = s; r.l = e; return r;
}
__device__ __forceinline__ df df_quick(float a, float b) {
    float s = __fadd_rn(a, b);
    float e = __fsub_rn(b, __fsub_rn(s, a));
    df r; r.h = s; r.l = e; return r;
}
__device__ __forceinline__ df df_add(df a, df b) {
    df s = df_two_sum(a.h, b.h);
    float e = __fadd_rn(s.l, __fadd_rn(a.l, b.l));
    return df_quick(s.h, e);
}
__device__ __forceinline__ df df_mul(df a, df b) {
    float p = __fmul_rn(a.h, b.h);
    float e = __fmaf_rn(a.h, b.h, -p);
    e = __fmaf_rn(a.h, b.l, e);
    e = __fmaf_rn(a.l, b.h, e);
    return df_quick(p, e);
}
#define DF_HI(x) ((float)(x))
#define DF_LO(x) ((float)((x) - (double)(float)(x)))
#define DF_CONST(x) { DF_HI(x), DF_LO(x) }

__device__ __forceinline__ float exp_hp(float x) {
    const float LN2H = DF_HI(0.69314718055994530941723212145818);
    const float LN2L = DF_LO(0.69314718055994530941723212145818);
    float kf = rintf(__fmul_rn(x, 1.4426950408889634f));
    float t  = __fmul_rn(kf, LN2H);
    float te = __fmaf_rn(kf, LN2H, -t);       // exact product residue
    df r = df_two_sum(x, -t);
    r.l = __fsub_rn(r.l, __fmaf_rn(kf, LN2L, te));
    r = df_quick(r.h, r.l);
    const df C[13] = {
        DF_CONST(1.0), DF_CONST(1.0), DF_CONST(0.5),
        DF_CONST(1.0/6.0), DF_CONST(1.0/24.0), DF_CONST(1.0/120.0),
        DF_CONST(1.0/720.0), DF_CONST(1.0/5040.0), DF_CONST(1.0/40320.0),
        DF_CONST(1.0/362880.0), DF_CONST(1.0/3628800.0),
        DF_CONST(1.0/39916800.0), DF_CONST(1.0/479001600.0)
    };
    df p = C[12];
    #pragma unroll
    for (int n = 11; n >= 0; --n) p = df_add(df_mul(p, r), C[n]);
    return ldexpf(__fadd_rn(p.h, p.l), (int)kf);
}

// ---------------- K0: zero counts/flags/rowbits/mask(head rows) ----------------
__global__ void k_zero() {
    int idx = blockIdx.x * blockDim.x + threadIdx.x;
    int stride = gridDim.x * blockDim.x;
    if (idx < BATCH) g_count[idx] = 0;
    if (idx == 0) { g_flagA = 0; g_flagB = 0; }
    u64* rb = &g_rowbits[0][0];
    for (int i = idx; i < BATCH * WSTRIDE; i += stride) rb[i] = 0ull;
    for (int i = idx; i < BATCH * LRANK * WSTRIDE; i += stride) {
        int b = i / (LRANK * WSTRIDE);
        int rem = i - b * (LRANK * WSTRIDE);
        g_mask[b][rem / WSTRIDE][rem % WSTRIDE] = 0ull;
    }
}

// ---------------- K1: static-threshold compact ----------------
__global__ void k_compactS(const float4* __restrict__ scores4) {
    int b = blockIdx.y;
    const unsigned th = map_f32(0.99f);
    const float4* sp = scores4 + (size_t)b * (NANCH / 2);
    const int M = NANCH / 2;
    int S = gridDim.x * blockDim.x;
    int tid = blockIdx.x * blockDim.x + threadIdx.x;
    int bound = ((M + 2 * S - 1) / (2 * S)) * (2 * S);
    unsigned lanebit = 1u << (threadIdx.x & 31);
    for (int i = tid; i < bound; i += 2 * S) {
        bool in0 = i < M, in1 = i + S < M;
        unsigned m0 = 0, m1 = 0, m2 = 0, m3 = 0;
        if (in0) { float4 v = sp[i];     m0 = map_f32(v.y); m1 = map_f32(v.w); }
        if (in1) { float4 v = sp[i + S]; m2 = map_f32(v.y); m3 = map_f32(v.w); }
        bool p0 = in0 && m0 >= th, p1 = in0 && m1 >= th;
        bool p2 = in1 && m2 >= th, p3 = in1 && m3 >= th;
        unsigned b0 = __ballot_sync(0xffffffffu, p0);
        unsigned b1 = __ballot_sync(0xffffffffu, p1);
        unsigned b2 = __ballot_sync(0xffffffffu, p2);
        unsigned b3 = __ballot_sync(0xffffffffu, p3);
        int c0 = __popc(b0), c1 = __popc(b1), c2 = __popc(b2), c3 = __popc(b3);
        int ctot = c0 + c1 + c2 + c3;
        if (ctot) {
            int base = 0;
            if ((threadIdx.x & 31) == 0) base = atomicAdd(&g_count[b], ctot);
            base = __shfl_sync(0xffffffffu, base, 0);
            if (p0) { int pos = base + __popc(b0 & (lanebit - 1));
                if (pos < CAND_CAP) g_cand[b][pos] = ((u64)m0 << 32) | (u64)(0xFFFFFFFFu - (unsigned)(2 * i)); }
            if (p1) { int pos = base + c0 + __popc(b1 & (lanebit - 1));
                if (pos < CAND_CAP) g_cand[b][pos] = ((u64)m1 << 32) | (u64)(0xFFFFFFFFu - (unsigned)(2 * i + 1)); }
            if (p2) { int pos = base + c0 + c1 + __popc(b2 & (lanebit - 1));
                if (pos < CAND_CAP) g_cand[b][pos] = ((u64)m2 << 32) | (u64)(0xFFFFFFFFu - (unsigned)(2 * (i + S))); }
            if (p3) { int pos = base + c0 + c1 + c2 + __popc(b3 & (lanebit - 1));
                if (pos < CAND_CAP) g_cand[b][pos] = ((u64)m3 << 32) | (u64)(0xFFFFFFFFu - (unsigned)(2 * (i + S) + 1)); }
        }
    }
}

// ---------------- K2: verify candidate counts; arm fallback ----------------
__global__ void k_check() {
    int t = threadIdx.x;
    __shared__ int bad;
    if (t == 0) bad = 0;
    __syncthreads();
    if (t < BATCH) {
        int c = g_count[t];
        if (c < KPRE || c > CAND_CAP) atomicExch(&bad, 1);
    }
    __syncthreads();
    if (t == 0) g_flagA = bad;
    __syncthreads();
    if (bad && t < BATCH) g_count[t] = 0;
}

// ---------------- gated fallback chain ----------------
__global__ void k_zeroF() {
    if (!g_flagA) return;
    int idx = blockIdx.x * blockDim.x + threadIdx.x;
    int stride = gridDim.x * blockDim.x;
    unsigned* h = &g_hist[0][0];
    for (int i = idx; i < BATCH * NBINS; i += stride) h[i] = 0u;
}
__global__ void k_histF(const float4* __restrict__ scores4) {
    if (!g_flagA) return;
    int b = blockIdx.y;
    const float4* sp = scores4 + (size_t)b * (NANCH / 2);
    const int M = NANCH / 2;
    int S = gridDim.x * blockDim.x;
    for (int i = blockIdx.x * blockDim.x + threadIdx.x; i < M; i += S) {
        float4 v = sp[i];
        atomicAdd(&g_hist[b][map_f32(v.y) >> 16], 1u);
        atomicAdd(&g_hist[b][map_f32(v.w) >> 16], 1u);
    }
}
__global__ void k_threshF() {
    if (!g_flagA) return;
    int b = blockIdx.x;
    __shared__ unsigned csum[256];
    unsigned s = 0;
    int c = threadIdx.x;
    for (int k = 0; k < 256; k++) s += g_hist[b][c * 256 + k];
    csum[c] = s;
    __syncthreads();
    if (threadIdx.x == 0) {
        unsigned cum = 0;
        int chunk = 255;
        while (chunk > 0 && cum + csum[chunk] < (unsigned)KPRE) { cum += csum[chunk]; chunk--; }
        int bin = chunk * 256 + 255;
        while (bin > chunk * 256 && cum + g_hist[b][bin] < (unsigned)KPRE) { cum += g_hist[b][bin]; bin--; }
        g_thresh[b] = (unsigned)bin << 16;
    }
}
__global__ void k_compactF(const float4* __restrict__ scores4) {
    if (!g_flagA) return;
    int b = blockIdx.y;
    unsigned th = g_thresh[b];
    const float4* sp = scores4 + (size_t)b * (NANCH / 2);
    const int M = NANCH / 2;
    int S = gridDim.x * blockDim.x;
    int tid = blockIdx.x * blockDim.x + threadIdx.x;
    int bound = ((M + S - 1) / S) * S;
    unsigned lanebit = 1u << (threadIdx.x & 31);
    for (int i = tid; i < bound; i += S) {
        bool in = i < M;
        unsigned m0 = 0, m1 = 0;
        if (in) { float4 v = sp[i]; m0 = map_f32(v.y); m1 = map_f32(v.w); }
        bool p0 = in && m0 >= th, p1 = in && m1 >= th;
        unsigned b0 = __ballot_sync(0xffffffffu, p0);
        unsigned b1 = __ballot_sync(0xffffffffu, p1);
        int c0 = __popc(b0), c1 = __popc(b1);
        if (c0 + c1) {
            int base = 0;
            if ((threadIdx.x & 31) == 0) base = atomicAdd(&g_count[b], c0 + c1);
            base = __shfl_sync(0xffffffffu, base, 0);
            if (p0) { int pos = base + __popc(b0 & (lanebit - 1));
                if (pos < CAND_CAP) g_cand[b][pos] = ((u64)m0 << 32) | (u64)(0xFFFFFFFFu - (unsigned)(2 * i)); }
            if (p1) { int pos = base + c0 + __popc(b1 & (lanebit - 1));
                if (pos < CAND_CAP) g_cand[b][pos] = ((u64)m1 << 32) | (u64)(0xFFFFFFFFu - (unsigned)(2 * i + 1)); }
        }
    }
}

// ---------------- K4: refine to fine threshold (1024 bins); compact -> g_cand2 ------
__global__ void k_refine() {
    int b = blockIdx.x;
    __shared__ int h[1024];
    __shared__ int pos;
    __shared__ unsigned s_th;
    int cnt = g_count[b];
    if (cnt > CAND_CAP) cnt = CAND_CAP;
    unsigned base = g_flagA ? g_thresh[b] : map_f32(0.99f);
    for (int i = threadIdx.x; i < 1024; i += blockDim.x) h[i] = 0;
    if (threadIdx.x == 0) pos = 0;
    __syncthreads();
    for (int i = threadIdx.x; i < cnt; i += blockDim.x) {
        unsigned m = (unsigned)(g_cand[b][i] >> 32);
        unsigned d = m - base;
        int bin = (int)(d >> 8);
        if (bin > 1023) bin = 1023;
        atomicAdd(&h[bin], 1);
    }
    __syncthreads();
    if (threadIdx.x == 0) {
        int cum = 0, sb = 1023;
        while (sb > 0 && cum + h[sb] < KPRE) { cum += h[sb]; sb--; }
        s_th = base + ((unsigned)sb << 8);
    }
    __syncthreads();
    for (int i = threadIdx.x; i < SORT_N; i += blockDim.x) g_cand2[b][i] = 0ull;
    __syncthreads();
    unsigned th = s_th;
    int bound = ((cnt + blockDim.x - 1) / blockDim.x) * blockDim.x;
    unsigned lanebit = 1u << (threadIdx.x & 31);
    for (int i = threadIdx.x; i < bound; i += blockDim.x) {
        u64 key = (i < cnt) ? g_cand[b][i] : 0ull;
        bool p = (i < cnt) && ((unsigned)(key >> 32) >= th);
        unsigned bl = __ballot_sync(0xffffffffu, p);
        if (bl) {
            int basep = 0;
            if ((threadIdx.x & 31) == 0) basep = atomicAdd(&pos, __popc(bl));
            basep = __shfl_sync(0xffffffffu, basep, 0);
            if (p) {
                int o = basep + __popc(bl & (lanebit - 1));
                if (o < SORT_N) g_cand2[b][o] = key;
            }
        }
    }
}

// ---------------- K5: sort 256-key chunks of g_cand2 (descending bitonic) ----------
__global__ void k_sort256() {
    __shared__ u64 keys[CHUNK];
    int b = blockIdx.y;
    int base = blockIdx.x * CHUNK;
    int t = threadIdx.x;
    keys[t] = g_cand2[b][base + t];
    __syncthreads();
    for (int k = 2; k <= CHUNK; k <<= 1) {
        for (int j = k >> 1; j > 0; j >>= 1) {
            int ixj = t ^ j;
            if (ixj > t) {
                bool desc = ((t & k) == 0);
                u64 a = keys[t], c = keys[ixj];
                bool swap = desc ? (a < c) : (a > c);
                if (swap) { keys[t] = c; keys[ixj] = a; }
            }
            __syncthreads();
        }
    }
    g_cand2[b][base + t] = keys[t];
}

// ---------------- K6: merge-path pass (descending, stable) ----------------
// dir=0: g_cand2 -> g_cand ; dir=1: g_cand -> g_cand2
__global__ void k_mergepass(int dir, int run) {
    int e = blockIdx.x * blockDim.x + threadIdx.x;
    int b = blockIdx.y;
    const u64* s = dir ? &g_cand[b][0] : &g_cand2[b][0];
    u64*       d = dir ? &g_cand2[b][0] : &g_cand[b][0];
    int base = e & ~(2 * run - 1);
    int local = e - base;
    u64 x = s[e];
    int pos;
    if (local < run) {
        const u64* B = s + base + run;
        int lo = 0, hi = run;
        while (lo < hi) { int mid = (lo + hi) >> 1; if (B[mid] > x) lo = mid + 1; else hi = mid; }
        pos = base + local + lo;
    } else {
        const u64* A = s + base;
        int j = local - run;
        int lo = 0, hi = run;
        while (lo < hi) { int mid = (lo + hi) >> 1; if (A[mid] >= x) lo = mid + 1; else hi = mid; }
        pos = base + lo + j;
    }
    d[pos] = x;
}

// ---------------- K7: decode boxes (df64 exp, no FP64) ----------------
__global__ void k_boxes(const float4* __restrict__ deltas,
                        const float4* __restrict__ anchors) {
    int b = blockIdx.y;
    int r = blockIdx.x * blockDim.x + threadIdx.x;
    if (r >= KPRE) return;
    u64 key = g_cand[b][r];
    unsigned idx = 0xFFFFFFFFu - (unsigned)(key & 0xFFFFFFFFull);
    if (idx >= NANCH) idx = 0;
    float4 an = anchors[idx];
    float4 dl = deltas[(size_t)b * NANCH + idx];
    float d0 = __fmul_rn(dl.x, 0.1f);
    float d1 = __fmul_rn(dl.y, 0.1f);
    float d2 = __fmul_rn(dl.z, 0.2f);
    float d3 = __fmul_rn(dl.w, 0.2f);
    float h = __fsub_rn(an.z, an.x);
    float w = __fsub_rn(an.w, an.y);
    float cy = __fadd_rn(__fadd_rn(an.x, __fmul_rn(0.5f, h)), __fmul_rn(d0, h));
    float cx = __fadd_rn(__fadd_rn(an.y, __fmul_rn(0.5f, w)), __fmul_rn(d1, w));
    float e2 = exp_hp(d2);
    float e3 = exp_hp(d3);
    float h2 = __fmul_rn(h, e2);
    float w2 = __fmul_rn(w, e3);
    float y1 = __fsub_rn(cy, __fmul_rn(0.5f, h2));
    float x1 = __fsub_rn(cx, __fmul_rn(0.5f, w2));
    float y2 = __fadd_rn(y1, h2);
    float x2 = __fadd_rn(x1, w2);
    y1 = fminf(fmaxf(y1, 0.f), 1.f);
    x1 = fminf(fmaxf(x1, 0.f), 1.f);
    y2 = fminf(fmaxf(y2, 0.f), 1.f);
    x2 = fminf(fmaxf(x2, 0.f), 1.f);
    g_boxes[b][r] = make_float4(y1, x1, y2, x2);
    g_areas[b][r] = __fmul_rn(__fsub_rn(y2, y1), __fsub_rn(x2, x1));
}

// ---------------- K8: head/tail spatial counting sort + tile AABBs ----------------
__global__ void k_spatial() {
    int b = blockIdx.x;
    __shared__ int hist[512];
    __shared__ int offs[512];
    __shared__ unsigned short mcell[KPRE];
    int t = threadIdx.x;
    for (int k = t; k < 512; k += blockDim.x) hist[k] = 0;
    __syncthreads();
    for (int r = t; r < KPRE; r += blockDim.x) {
        float4 bx = g_boxes[b][r];
        float cy = 0.5f * (bx.x + bx.z);
        float cx = 0.5f * (bx.y + bx.w);
        int iy = (int)(cy * 16.f); iy = iy < 0 ? 0 : (iy > 15 ? 15 : iy);
        int ix = (int)(cx * 16.f); ix = ix < 0 ? 0 : (ix > 15 ? 15 : ix);
        int m = 0;
        #pragma unroll
        for (int k = 0; k < 4; k++)
            m |= (((iy >> k) & 1) << (2 * k + 1)) | (((ix >> k) & 1) << (2 * k));
        int key = ((r < LRANK) ? 0 : 256) + m;
        mcell[r] = (unsigned short)key;
        atomicAdd(&hist[key], 1);
    }
    __syncthreads();
    if (t == 0) {
        int run = 0;
        for (int k = 0; k < 512; k++) { offs[k] = run; run += hist[k]; }
    }
    __syncthreads();
    for (int r = t; r < KPRE; r += blockDim.x) {
        int key = mcell[r];
        int pos = atomicAdd(&offs[key], 1);
        g_sbox[b][pos] = g_boxes[b][r];
        g_sarea[b][pos] = g_areas[b][r];
        g_srank[b][pos] = r;
    }
    if (t < NSLOT - KPRE) {
        int pos = KPRE + t;
        g_sbox[b][pos] = make_float4(9e9f, 9e9f, -9e9f, -9e9f);
        g_sarea[b][pos] = 0.f;
        g_srank[b][pos] = 0;
    }
    __syncthreads();
    if (t < TILES) {
        float miny = 9e9f, minx = 9e9f, maxy = -9e9f, maxx = -9e9f;
        #pragma unroll 4
        for (int e = 0; e < 64; e++) {
            float4 bx = g_sbox[b][t * 64 + e];
            miny = fminf(miny, bx.x); minx = fminf(minx, bx.y);
            maxy = fmaxf(maxy, bx.z); maxx = fmaxf(maxx, bx.w);
        }
        g_aabb[b][t] = make_float4(miny, minx, maxy, maxx);
    }
}

// ---------------- shared pair-tile body ----------------
__device__ __forceinline__ void pair_tiles(int b, int ta, int tb) {
    float4 aA = g_aabb[b][ta];
    float4 aB = g_aabb[b][tb];
    if (!(aA.z > aB.x && aB.z > aA.x && aA.w > aB.y && aB.w > aA.y)) return;
    __shared__ float4 sb4[64];
    __shared__ float  sar[64];
    __shared__ int    srk[64];
    int t = threadIdx.x;
    int row = t & 63;
    int half = t >> 6;
    if (t < 64) {
        int s = tb * 64 + t;
        sb4[t] = g_sbox[b][s];
        sar[t] = g_sarea[b][s];
        srk[t] = g_srank[b][s];
    }
    __syncthreads();
    int sa = ta * 64 + row;
    float4 bi = g_sbox[b][sa];
    float  ai = g_sarea[b][sa];
    int ra = g_srank[b][sa];
    if (!(bi.z > aB.x && aB.z > bi.x && bi.w > aB.y && aB.w > bi.y)) return;
    bool diag = (ta == tb);
    int j0 = half * 32;
    #pragma unroll 4
    for (int jj = j0; jj < j0 + 32; ++jj) {
        if (diag && jj <= row) continue;
        float4 bj = sb4[jj];
        float yy1 = fmaxf(bi.x, bj.x);
        float xx1 = fmaxf(bi.y, bj.y);
        float yy2 = fminf(bi.z, bj.z);
        float xx2 = fminf(bi.w, bj.w);
        float dh = __fsub_rn(yy2, yy1);
        float dw = __fsub_rn(xx2, xx1);
        if (dh > 0.f && dw > 0.f) {
            float inter = __fmul_rn(dh, dw);
            float u = __fsub_rn(__fadd_rn(ai, sar[jj]), inter);
            if (u > 0.f) {
                bool sup;
                if (inter > __fmul_rn(0.71f, u)) sup = true;
                else if (inter >= __fmul_rn(0.69f, u)) sup = __fdiv_rn(inter, u) > 0.7f;
                else sup = false;
                if (sup) {
                    int rb = srk[jj];
                    int rmin = ra < rb ? ra : rb;
                    int rmax = ra < rb ? rb : ra;
                    atomicOr(&g_mask[b][rmin][rmax >> 6], 1ull << (rmax & 63));
                    atomicOr(&g_rowbits[b][rmin >> 6], 1ull << (rmin & 63));
                }
            }
        }
    }
}

// ---------------- K9: pairs with at least one head tile ----------------
__global__ void k_pairs() {
    int ta = blockIdx.x;
    int hb = blockIdx.y;
    if (ta < hb) return;
    pair_tiles(blockIdx.z, ta, hb);
}

// ---------------- gated: tail fixups ----------------
__global__ void k_zeroTailF() {
    if (!g_flagB) return;
    int idx = blockIdx.x * blockDim.x + threadIdx.x;
    int stride = gridDim.x * blockDim.x;
    const int n = BATCH * (KPRE - LRANK) * WSTRIDE;
    for (int i = idx; i < n; i += stride) {
        int b = i / ((KPRE - LRANK) * WSTRIDE);
        int rem = i - b * ((KPRE - LRANK) * WSTRIDE);
        g_mask[b][LRANK + rem / WSTRIDE][rem % WSTRIDE] = 0ull;
    }
}
__global__ void k_pairsTailF() {
    if (!g_flagB) return;
    int ta = HTILES + blockIdx.x;
    int tb = HTILES + blockIdx.y;
    if (ta < tb) return;
    pair_tiles(blockIdx.z, ta, tb);
}

// ---------------- K10: greedy reduce ----------------
__global__ void k_reduce(float* __restrict__ out, int mode) {
    if (mode == 1 && !g_flagB) return;
    int b = blockIdx.x;
    int lane = threadIdx.x;
    __shared__ int sel[KOUT];
    u64 rm0 = 0ull, rm1 = 0ull, rm2 = 0ull;
    const u64* mask = &g_mask[b][0][0];
    u64 hb0 = g_rowbits[b][lane];
    u64 hb1 = g_rowbits[b][lane + 32];
    u64 hb2 = (lane + 64 < WORDS) ? g_rowbits[b][lane + 64] : 0ull;
    int cnt = 0;

    for (int w = 0; w < WORDS && cnt < KOUT; ++w) {
        int slot = w >> 5;
        int owner = w & 31;
        u64 rmv = (slot == 0) ? rm0 : ((slot == 1) ? rm1 : rm2);
        u64 hbv = (slot == 0) ? hb0 : ((slot == 1) ? hb1 : hb2);
        u64 cur = __shfl_sync(0xffffffffu, rmv, owner);
        u64 hasw = __shfl_sync(0xffffffffu, hbv, owner);
        u64 wm = (w == WORDS - 1) ? ((1ull << 48) - 1) : ~0ull;
        u64 valid = ~cur & wm;

        {
            u64 pf = valid & hasw;
            #pragma unroll
            for (int c = 0; c < 2; c++) {
                if (!pf) break;
                int nb = __ffsll((long long)pf) - 1;
                pf &= pf - 1;
                const char* p = (const char*)(mask + (size_t)((w << 6) + nb) * WSTRIDE);
                if ((lane >> 3) == c && (lane & 7) < 6)
                    asm volatile("prefetch.global.L1 [%0];" :: "l"(p + (lane & 7) * 128));
            }
        }

        while (valid) {
            int bpos = __ffsll((long long)valid) - 1;
            int i = (w << 6) + bpos;
            if (lane == 0) {
                sel[cnt] = i;
                if (mode == 0 && i >= LRANK) g_flagB = 1;
            }
            cnt++;
            if (cnt >= KOUT) break;
            if ((hasw >> bpos) & 1ull) {
                const u64* rowp = mask + (size_t)i * WSTRIDE;
                u64 r0 = __ldg(rowp + lane);
                u64 r1 = __ldg(rowp + lane + 32);
                u64 r2 = (lane + 64 < WORDS) ? __ldg(rowp + lane + 64) : 0ull;
                rm0 |= r0;
                rm1 |= r1;
                rm2 |= r2;
                u64 rw = (slot == 0) ? r0 : ((slot == 1) ? r1 : r2);
                cur |= __shfl_sync(0xffffffffu, rw, owner);
                u64 above = (bpos == 63) ? 0ull : (~0ull << (bpos + 1));
                valid = ~cur & wm & above;
                u64 pf = valid & hasw;
                #pragma unroll
                for (int c = 0; c < 2; c++) {
                    if (!pf) break;
                    int nb = __ffsll((long long)pf) - 1;
                    pf &= pf - 1;
                    const char* p = (const char*)(mask + (size_t)((w << 6) + nb) * WSTRIDE);
                    if ((lane >> 3) == c && (lane & 7) < 6)
                        asm volatile("prefetch.global.L1 [%0];" :: "l"(p + (lane & 7) * 128));
                }
            } else {
                u64 above = (bpos == 63) ? 0ull : (~0ull << (bpos + 1));
                valid &= above;
            }
        }
    }
    __syncwarp();

    float4* o = (float4*)(out + (size_t)b * KOUT * 4);
    for (int r = lane; r < KOUT; r += 32) {
        float4 v = make_float4(0.f, 0.f, 0.f, 0.f);
        if (r < cnt) v = g_boxes[b][sel[r]];
        o[r] = v;
    }
}

// ---------------- launch ----------------
extern "C" void kernel_launch(void* const* d_in, const int* in_sizes, int n_in,
                              void* d_out, int out_size) {
    const float4* scores4 = (const float4*)d_in[0];
    const float4* deltas  = (const float4*)d_in[1];
    const float4* anchors = (const float4*)d_in[2];
    float* out = (float*)d_out;

    k_zero<<<512, 1024>>>();
    {
        dim3 g(128, BATCH);
        k_compactS<<<g, 256>>>(scores4);
    }
    k_check<<<1, 32>>>();
    // gated fallback chain (no-ops when flagA == 0)
    k_zeroF<<<32, 1024>>>();
    {
        dim3 g(128, BATCH);
        k_histF<<<g, 256>>>(scores4);
    }
    k_threshF<<<BATCH, 256>>>();
    {
        dim3 g(128, BATCH);
        k_compactF<<<g, 256>>>(scores4);
    }
    k_refine<<<BATCH, 512>>>();
    {
        dim3 g(NCHUNK, BATCH);
        k_sort256<<<g, CHUNK>>>();
    }
    {
        dim3 g(SORT_N / 256, BATCH);
        k_mergepass<<<g, 256>>>(0, 256);    // cand2 -> cand
        k_mergepass<<<g, 256>>>(1, 512);    // cand  -> cand2
        k_mergepass<<<g, 256>>>(0, 1024);   // cand2 -> cand
        k_mergepass<<<g, 256>>>(1, 2048);   // cand  -> cand2
        k_mergepass<<<g, 256>>>(0, 4096);   // cand2 -> cand (final, sorted 8192)
    }
    {
        dim3 g((KPRE + 255) / 256, BATCH);
        k_boxes<<<g, 256>>>(deltas, anchors);
    }
    k_spatial<<<BATCH, 256>>>();
    {
        dim3 g(TILES, HTILES, BATCH);
        k_pairs<<<g, 128>>>();
    }
    k_reduce<<<BATCH, 32>>>(out, 0);
    k_zeroTailF<<<256, 1024>>>();
    {
        dim3 g(TTILES, TTILES, BATCH);
        k_pairsTailF<<<g, 128>>>();
    }
    k_reduce<<<BATCH, 32>>>(out, 1);
}

// round 8
// speedup vs baseline: 3.1852x; 1.0414x over previous
#include <cuda_runtime.h>
#include <cstdint>
#include <math.h>

#define BATCH     8
#define NANCH     1047552
#define KPRE      6000
#define KOUT      1000
#define CAND_CAP  16384
#define SORT_N    8192
#define CHUNK2    2048
#define NCHUNK2   (SORT_N / CHUNK2)
#define WORDS     94
#define WSTRIDE   96
#define NBINS     65536
#define TILES     94
#define NSLOT     (TILES*64)
#define LRANK     2560
#define HTILES    40
#define TTILES    54

typedef unsigned long long u64;

// ---------------- device scratch ----------------
__device__ __align__(128) unsigned int g_hist[BATCH][NBINS];
__device__ __align__(128) unsigned int g_thresh[BATCH];
__device__ __align__(128) int          g_count[BATCH];
__device__ int g_flagA;
__device__ int g_flagB;
__device__ __align__(128) u64          g_cand[BATCH][CAND_CAP];
__device__ __align__(128) u64          g_cand2[BATCH][SORT_N];
__device__ __align__(128) float4       g_boxes[BATCH][KPRE];
__device__ __align__(128) float        g_areas[BATCH][KPRE];
__device__ __align__(128) u64          g_mask[BATCH][KPRE][WSTRIDE];
__device__ __align__(128) u64          g_rowbits[BATCH][WSTRIDE];
__device__ __align__(128) float4       g_sbox[BATCH][NSLOT];
__device__ __align__(128) float        g_sarea[BATCH][NSLOT];
__device__ __align__(128) int          g_srank[BATCH][NSLOT];
__device__ __align__(128) float4       g_aabb[BATCH][TILES];

__device__ __forceinline__ unsigned map_f32(float v) {
    unsigned b = __float_as_uint(v);
    return b ^ ((b & 0x80000000u) ? 0xFFFFFFFFu : 0x80000000u);
}

// ============ double-float exp (f32-only), validated bit-stable in R7 ============
struct df { float h, l; };
__device__ __forceinline__ df df_two_sum(float a, float b) {
    float s = __fadd_rn(a, b);
    float v = __fsub_rn(s, a);
    float e = __fadd_rn(__fsub_rn(a, __fsub_rn(s, v)), __fsub_rn(b, v));
    df r; r.h = s; r.l = e; return r;
}
__device__ __forceinline__ df df_quick(float a, float b) {
    float s = __fadd_rn(a, b);
    float e = __fsub_rn(b, __fsub_rn(s, a));
    df r; r.h = s; r.l = e; return r;
}
__device__ __forceinline__ df df_add(df a, df b) {
    df s = df_two_sum(a.h, b.h);
    float e = __fadd_rn(s.l, __fadd_rn(a.l, b.l));
    return df_quick(s.h, e);
}
__device__ __forceinline__ df df_mul(df a, df b) {
    float p = __fmul_rn(a.h, b.h);
    float e = __fmaf_rn(a.h, b.h, -p);
    e = __fmaf_rn(a.h, b.l, e);
    e = __fmaf_rn(a.l, b.h, e);
    return df_quick(p, e);
}
#define DF_HI(x) ((float)(x))
#define DF_LO(x) ((float)((x) - (double)(float)(x)))
#define DF_CONST(x) { DF_HI(x), DF_LO(x) }

__device__ __forceinline__ float exp_hp(float x) {
    const float LN2H = DF_HI(0.69314718055994530941723212145818);
    const float LN2L = DF_LO(0.69314718055994530941723212145818);
    float kf = rintf(__fmul_rn(x, 1.4426950408889634f));
    float t  = __fmul_rn(kf, LN2H);
    float te = __fmaf_rn(kf, LN2H, -t);
    df r = df_two_sum(x, -t);
    r.l = __fsub_rn(r.l, __fmaf_rn(kf, LN2L, te));
    r = df_quick(r.h, r.l);
    const df C[13] = {
        DF_CONST(1.0), DF_CONST(1.0), DF_CONST(0.5),
        DF_CONST(1.0/6.0), DF_CONST(1.0/24.0), DF_CONST(1.0/120.0),
        DF_CONST(1.0/720.0), DF_CONST(1.0/5040.0), DF_CONST(1.0/40320.0),
        DF_CONST(1.0/362880.0), DF_CONST(1.0/3628800.0),
        DF_CONST(1.0/39916800.0), DF_CONST(1.0/479001600.0)
    };
    df p = C[12];
    #pragma unroll
    for (int n = 11; n >= 0; --n) p = df_add(df_mul(p, r), C[n]);
    return ldexpf(__fadd_rn(p.h, p.l), (int)kf);
}

// ---------------- K0: zero counts/flags/rowbits/mask(head rows) ----------------
__global__ void k_zero() {
    int idx = blockIdx.x * blockDim.x + threadIdx.x;
    int stride = gridDim.x * blockDim.x;
    if (idx < BATCH) g_count[idx] = 0;
    if (idx == 0) { g_flagA = 0; g_flagB = 0; }
    u64* rb = &g_rowbits[0][0];
    for (int i = idx; i < BATCH * WSTRIDE; i += stride) rb[i] = 0ull;
    for (int i = idx; i < BATCH * LRANK * WSTRIDE; i += stride) {
        int b = i / (LRANK * WSTRIDE);
        int rem = i - b * (LRANK * WSTRIDE);
        g_mask[b][rem / WSTRIDE][rem % WSTRIDE] = 0ull;
    }
}

// ---------------- K1: static-threshold compact ----------------
__global__ void k_compactS(const float4* __restrict__ scores4) {
    int b = blockIdx.y;
    const unsigned th = map_f32(0.99f);
    const float4* sp = scores4 + (size_t)b * (NANCH / 2);
    const int M = NANCH / 2;
    int S = gridDim.x * blockDim.x;
    int tid = blockIdx.x * blockDim.x + threadIdx.x;
    int bound = ((M + 2 * S - 1) / (2 * S)) * (2 * S);
    unsigned lanebit = 1u << (threadIdx.x & 31);
    for (int i = tid; i < bound; i += 2 * S) {
        bool in0 = i < M, in1 = i + S < M;
        unsigned m0 = 0, m1 = 0, m2 = 0, m3 = 0;
        if (in0) { float4 v = sp[i];     m0 = map_f32(v.y); m1 = map_f32(v.w); }
        if (in1) { float4 v = sp[i + S]; m2 = map_f32(v.y); m3 = map_f32(v.w); }
        bool p0 = in0 && m0 >= th, p1 = in0 && m1 >= th;
        bool p2 = in1 && m2 >= th, p3 = in1 && m3 >= th;
        unsigned b0 = __ballot_sync(0xffffffffu, p0);
        unsigned b1 = __ballot_sync(0xffffffffu, p1);
        unsigned b2 = __ballot_sync(0xffffffffu, p2);
        unsigned b3 = __ballot_sync(0xffffffffu, p3);
        int c0 = __popc(b0), c1 = __popc(b1), c2 = __popc(b2), c3 = __popc(b3);
        int ctot = c0 + c1 + c2 + c3;
        if (ctot) {
            int base = 0;
            if ((threadIdx.x & 31) == 0) base = atomicAdd(&g_count[b], ctot);
            base = __shfl_sync(0xffffffffu, base, 0);
            if (p0) { int pos = base + __popc(b0 & (lanebit - 1));
                if (pos < CAND_CAP) g_cand[b][pos] = ((u64)m0 << 32) | (u64)(0xFFFFFFFFu - (unsigned)(2 * i)); }
            if (p1) { int pos = base + c0 + __popc(b1 & (lanebit - 1));
                if (pos < CAND_CAP) g_cand[b][pos] = ((u64)m1 << 32) | (u64)(0xFFFFFFFFu - (unsigned)(2 * i + 1)); }
            if (p2) { int pos = base + c0 + c1 + __popc(b2 & (lanebit - 1));
                if (pos < CAND_CAP) g_cand[b][pos] = ((u64)m2 << 32) | (u64)(0xFFFFFFFFu - (unsigned)(2 * (i + S))); }
            if (p3) { int pos = base + c0 + c1 + c2 + __popc(b3 & (lanebit - 1));
                if (pos < CAND_CAP) g_cand[b][pos] = ((u64)m3 << 32) | (u64)(0xFFFFFFFFu - (unsigned)(2 * (i + S) + 1)); }
        }
    }
}

// ---------------- K2: verify counts; arm fallback ----------------
__global__ void k_check() {
    int t = threadIdx.x;
    __shared__ int bad;
    if (t == 0) bad = 0;
    __syncthreads();
    if (t < BATCH) {
        int c = g_count[t];
        if (c < KPRE || c > CAND_CAP) atomicExch(&bad, 1);
    }
    __syncthreads();
    if (t == 0) g_flagA = bad;
    __syncthreads();
    if (bad && t < BATCH) g_count[t] = 0;
}

// ---------------- gated fallback chain (tiny grids; never taken normally) --------
__global__ void k_zeroF() {
    if (!g_flagA) return;
    int idx = blockIdx.x * blockDim.x + threadIdx.x;
    int stride = gridDim.x * blockDim.x;
    unsigned* h = &g_hist[0][0];
    for (int i = idx; i < BATCH * NBINS; i += stride) h[i] = 0u;
}
__global__ void k_histF(const float4* __restrict__ scores4) {
    if (!g_flagA) return;
    int b = blockIdx.y;
    const float4* sp = scores4 + (size_t)b * (NANCH / 2);
    const int M = NANCH / 2;
    int S = gridDim.x * blockDim.x;
    for (int i = blockIdx.x * blockDim.x + threadIdx.x; i < M; i += S) {
        float4 v = sp[i];
        atomicAdd(&g_hist[b][map_f32(v.y) >> 16], 1u);
        atomicAdd(&g_hist[b][map_f32(v.w) >> 16], 1u);
    }
}
__global__ void k_threshF() {
    if (!g_flagA) return;
    int b = blockIdx.x;
    __shared__ unsigned csum[256];
    unsigned s = 0;
    int c = threadIdx.x;
    for (int k = 0; k < 256; k++) s += g_hist[b][c * 256 + k];
    csum[c] = s;
    __syncthreads();
    if (threadIdx.x == 0) {
        unsigned cum = 0;
        int chunk = 255;
        while (chunk > 0 && cum + csum[chunk] < (unsigned)KPRE) { cum += csum[chunk]; chunk--; }
        int bin = chunk * 256 + 255;
        while (bin > chunk * 256 && cum + g_hist[b][bin] < (unsigned)KPRE) { cum += g_hist[b][bin]; bin--; }
        g_thresh[b] = (unsigned)bin << 16;
    }
}
__global__ void k_compactF(const float4* __restrict__ scores4) {
    if (!g_flagA) return;
    int b = blockIdx.y;
    unsigned th = g_thresh[b];
    const float4* sp = scores4 + (size_t)b * (NANCH / 2);
    const int M = NANCH / 2;
    int S = gridDim.x * blockDim.x;
    int tid = blockIdx.x * blockDim.x + threadIdx.x;
    int bound = ((M + S - 1) / S) * S;
    unsigned lanebit = 1u << (threadIdx.x & 31);
    for (int i = tid; i < bound; i += S) {
        bool in = i < M;
        unsigned m0 = 0, m1 = 0;
        if (in) { float4 v = sp[i]; m0 = map_f32(v.y); m1 = map_f32(v.w); }
        bool p0 = in && m0 >= th, p1 = in && m1 >= th;
        unsigned b0 = __ballot_sync(0xffffffffu, p0);
        unsigned b1 = __ballot_sync(0xffffffffu, p1);
        int c0 = __popc(b0), c1 = __popc(b1);
        if (c0 + c1) {
            int base = 0;
            if ((threadIdx.x & 31) == 0) base = atomicAdd(&g_count[b], c0 + c1);
            base = __shfl_sync(0xffffffffu, base, 0);
            if (p0) { int pos = base + __popc(b0 & (lanebit - 1));
                if (pos < CAND_CAP) g_cand[b][pos] = ((u64)m0 << 32) | (u64)(0xFFFFFFFFu - (unsigned)(2 * i)); }
            if (p1) { int pos = base + c0 + __popc(b1 & (lanebit - 1));
                if (pos < CAND_CAP) g_cand[b][pos] = ((u64)m1 << 32) | (u64)(0xFFFFFFFFu - (unsigned)(2 * i + 1)); }
        }
    }
}

// ---------------- K4: refine to fine threshold; compact -> g_cand2 ----------------
__global__ void k_refine() {
    int b = blockIdx.x;
    __shared__ int h[1024];
    __shared__ int pos;
    __shared__ unsigned s_th;
    int cnt = g_count[b];
    if (cnt > CAND_CAP) cnt = CAND_CAP;
    unsigned base = g_flagA ? g_thresh[b] : map_f32(0.99f);
    for (int i = threadIdx.x; i < 1024; i += blockDim.x) h[i] = 0;
    if (threadIdx.x == 0) pos = 0;
    __syncthreads();
    for (int i = threadIdx.x; i < cnt; i += blockDim.x) {
        unsigned m = (unsigned)(g_cand[b][i] >> 32);
        unsigned d = m - base;
        int bin = (int)(d >> 8);
        if (bin > 1023) bin = 1023;
        atomicAdd(&h[bin], 1);
    }
    __syncthreads();
    if (threadIdx.x == 0) {
        int cum = 0, sb = 1023;
        while (sb > 0 && cum + h[sb] < KPRE) { cum += h[sb]; sb--; }
        s_th = base + ((unsigned)sb << 8);
    }
    __syncthreads();
    for (int i = threadIdx.x; i < SORT_N; i += blockDim.x) g_cand2[b][i] = 0ull;
    __syncthreads();
    unsigned th = s_th;
    int bound = ((cnt + blockDim.x - 1) / blockDim.x) * blockDim.x;
    unsigned lanebit = 1u << (threadIdx.x & 31);
    for (int i = threadIdx.x; i < bound; i += blockDim.x) {
        u64 key = (i < cnt) ? g_cand[b][i] : 0ull;
        bool p = (i < cnt) && ((unsigned)(key >> 32) >= th);
        unsigned bl = __ballot_sync(0xffffffffu, p);
        if (bl) {
            int basep = 0;
            if ((threadIdx.x & 31) == 0) basep = atomicAdd(&pos, __popc(bl));
            basep = __shfl_sync(0xffffffffu, basep, 0);
            if (p) {
                int o = basep + __popc(bl & (lanebit - 1));
                if (o < SORT_N) g_cand2[b][o] = key;
            }
        }
    }
}

// ---------------- K5: sort 2048-key chunks of g_cand2 (descending bitonic) --------
__global__ void k_sort2048() {
    __shared__ u64 keys[CHUNK2];
    int b = blockIdx.y;
    int base = blockIdx.x * CHUNK2;
    int t = threadIdx.x;
    keys[t] = g_cand2[b][base + t];
    keys[t + 1024] = g_cand2[b][base + t + 1024];
    __syncthreads();
    for (int k = 2; k <= CHUNK2; k <<= 1) {
        for (int j = k >> 1; j > 0; j >>= 1) {
            #pragma unroll
            for (int u = 0; u < 2; u++) {
                int i = t + u * 1024;
                int ixj = i ^ j;
                if (ixj > i) {
                    bool desc = ((i & k) == 0);
                    u64 a = keys[i], c = keys[ixj];
                    if (desc ? (a < c) : (a > c)) { keys[i] = c; keys[ixj] = a; }
                }
            }
            __syncthreads();
        }
    }
    g_cand2[b][base + t] = keys[t];
    g_cand2[b][base + t + 1024] = keys[t + 1024];
}

// ---------------- K6: merge-path pass (descending, stable) ----------------
// dir=0: g_cand2 -> g_cand ; dir=1: g_cand -> g_cand2
__global__ void k_mergepass(int dir, int run) {
    int e = blockIdx.x * blockDim.x + threadIdx.x;
    int b = blockIdx.y;
    const u64* s = dir ? &g_cand[b][0] : &g_cand2[b][0];
    u64*       d = dir ? &g_cand2[b][0] : &g_cand[b][0];
    int base = e & ~(2 * run - 1);
    int local = e - base;
    u64 x = s[e];
    int pos;
    if (local < run) {
        const u64* B = s + base + run;
        int lo = 0, hi = run;
        while (lo < hi) { int mid = (lo + hi) >> 1; if (B[mid] > x) lo = mid + 1; else hi = mid; }
        pos = base + local + lo;
    } else {
        const u64* A = s + base;
        int j = local - run;
        int lo = 0, hi = run;
        while (lo < hi) { int mid = (lo + hi) >> 1; if (A[mid] >= x) lo = mid + 1; else hi = mid; }
        pos = base + lo + j;
    }
    d[pos] = x;
}

// ---------------- K7: decode boxes (reads final sorted keys in g_cand2) -----------
__global__ void k_boxes(const float4* __restrict__ deltas,
                        const float4* __restrict__ anchors) {
    int b = blockIdx.y;
    int r = blockIdx.x * blockDim.x + threadIdx.x;
    if (r >= KPRE) return;
    u64 key = g_cand2[b][r];
    unsigned idx = 0xFFFFFFFFu - (unsigned)(key & 0xFFFFFFFFull);
    if (idx >= NANCH) idx = 0;
    float4 an = anchors[idx];
    float4 dl = deltas[(size_t)b * NANCH + idx];
    float d0 = __fmul_rn(dl.x, 0.1f);
    float d1 = __fmul_rn(dl.y, 0.1f);
    float d2 = __fmul_rn(dl.z, 0.2f);
    float d3 = __fmul_rn(dl.w, 0.2f);
    float h = __fsub_rn(an.z, an.x);
    float w = __fsub_rn(an.w, an.y);
    float cy = __fadd_rn(__fadd_rn(an.x, __fmul_rn(0.5f, h)), __fmul_rn(d0, h));
    float cx = __fadd_rn(__fadd_rn(an.y, __fmul_rn(0.5f, w)), __fmul_rn(d1, w));
    float e2 = exp_hp(d2);
    float e3 = exp_hp(d3);
    float h2 = __fmul_rn(h, e2);
    float w2 = __fmul_rn(w, e3);
    float y1 = __fsub_rn(cy, __fmul_rn(0.5f, h2));
    float x1 = __fsub_rn(cx, __fmul_rn(0.5f, w2));
    float y2 = __fadd_rn(y1, h2);
    float x2 = __fadd_rn(x1, w2);
    y1 = fminf(fmaxf(y1, 0.f), 1.f);
    x1 = fminf(fmaxf(x1, 0.f), 1.f);
    y2 = fminf(fmaxf(y2, 0.f), 1.f);
    x2 = fminf(fmaxf(x2, 0.f), 1.f);
    g_boxes[b][r] = make_float4(y1, x1, y2, x2);
    g_areas[b][r] = __fmul_rn(__fsub_rn(y2, y1), __fsub_rn(x2, x1));
}

// ---------------- K8: head/tail spatial counting sort + tile AABBs ----------------
__global__ void k_spatial() {
    int b = blockIdx.x;
    __shared__ int hist[512];
    __shared__ int offs[512];
    __shared__ unsigned short mcell[KPRE];
    int t = threadIdx.x;
    for (int k = t; k < 512; k += blockDim.x) hist[k] = 0;
    __syncthreads();
    for (int r = t; r < KPRE; r += blockDim.x) {
        float4 bx = g_boxes[b][r];
        float cy = 0.5f * (bx.x + bx.z);
        float cx = 0.5f * (bx.y + bx.w);
        int iy = (int)(cy * 16.f); iy = iy < 0 ? 0 : (iy > 15 ? 15 : iy);
        int ix = (int)(cx * 16.f); ix = ix < 0 ? 0 : (ix > 15 ? 15 : ix);
        int m = 0;
        #pragma unroll
        for (int k = 0; k < 4; k++)
            m |= (((iy >> k) & 1) << (2 * k + 1)) | (((ix >> k) & 1) << (2 * k));
        int key = ((r < LRANK) ? 0 : 256) + m;
        mcell[r] = (unsigned short)key;
        atomicAdd(&hist[key], 1);
    }
    __syncthreads();
    if (t == 0) {
        int run = 0;
        for (int k = 0; k < 512; k++) { offs[k] = run; run += hist[k]; }
    }
    __syncthreads();
    for (int r = t; r < KPRE; r += blockDim.x) {
        int key = mcell[r];
        int pos = atomicAdd(&offs[key], 1);
        g_sbox[b][pos] = g_boxes[b][r];
        g_sarea[b][pos] = g_areas[b][r];
        g_srank[b][pos] = r;
    }
    if (t < NSLOT - KPRE) {
        int pos = KPRE + t;
        g_sbox[b][pos] = make_float4(9e9f, 9e9f, -9e9f, -9e9f);
        g_sarea[b][pos] = 0.f;
        g_srank[b][pos] = 0;
    }
    __syncthreads();
    if (t < TILES) {
        float miny = 9e9f, minx = 9e9f, maxy = -9e9f, maxx = -9e9f;
        #pragma unroll 4
        for (int e = 0; e < 64; e++) {
            float4 bx = g_sbox[b][t * 64 + e];
            miny = fminf(miny, bx.x); minx = fminf(minx, bx.y);
            maxy = fmaxf(maxy, bx.z); maxx = fmaxf(maxx, bx.w);
        }
        g_aabb[b][t] = make_float4(miny, minx, maxy, maxx);
    }
}

// ---------------- IoU pair body (single tile pair) ----------------
__device__ __forceinline__ void pair_tiles(int b, int ta, int tb) {
    float4 aA = g_aabb[b][ta];
    float4 aB = g_aabb[b][tb];
    if (!(aA.z > aB.x && aB.z > aA.x && aA.w > aB.y && aB.w > aA.y)) return;
    __shared__ float4 sb4[64];
    __shared__ float  sar[64];
    __shared__ int    srk[64];
    int t = threadIdx.x;
    int row = t & 63;
    int half = t >> 6;
    if (t < 64) {
        int s = tb * 64 + t;
        sb4[t] = g_sbox[b][s];
        sar[t] = g_sarea[b][s];
        srk[t] = g_srank[b][s];
    }
    __syncthreads();
    int sa = ta * 64 + row;
    float4 bi = g_sbox[b][sa];
    float  ai = g_sarea[b][sa];
    int ra = g_srank[b][sa];
    if (!(bi.z > aB.x && aB.z > bi.x && bi.w > aB.y && aB.w > bi.y)) return;
    bool diag = (ta == tb);
    int j0 = half * 32;
    #pragma unroll 4
    for (int jj = j0; jj < j0 + 32; ++jj) {
        if (diag && jj <= row) continue;
        float4 bj = sb4[jj];
        float yy1 = fmaxf(bi.x, bj.x);
        float xx1 = fmaxf(bi.y, bj.y);
        float yy2 = fminf(bi.z, bj.z);
        float xx2 = fminf(bi.w, bj.w);
        float dh = __fsub_rn(yy2, yy1);
        float dw = __fsub_rn(xx2, xx1);
        if (dh > 0.f && dw > 0.f) {
            float inter = __fmul_rn(dh, dw);
            float u = __fsub_rn(__fadd_rn(ai, sar[jj]), inter);
            if (u > 0.f) {
                bool sup;
                if (inter > __fmul_rn(0.71f, u)) sup = true;
                else if (inter >= __fmul_rn(0.69f, u)) sup = __fdiv_rn(inter, u) > 0.7f;
                else sup = false;
                if (sup) {
                    int rb = srk[jj];
                    int rmin = ra < rb ? ra : rb;
                    int rmax = ra < rb ? rb : ra;
                    atomicOr(&g_mask[b][rmin][rmax >> 6], 1ull << (rmax & 63));
                    atomicOr(&g_rowbits[b][rmin >> 6], 1ull << (rmin & 63));
                }
            }
        }
    }
}

// ---------------- K9: pairs with at least one head tile ----------------
__global__ void k_pairs() {
    int ta = blockIdx.x;
    int hb = blockIdx.y;
    if (ta < hb) return;
    pair_tiles(blockIdx.z, ta, hb);
}

// ---------------- gated: tail fixups (compact grids, loop inside block) -----------
__global__ void k_zeroTailF() {
    if (!g_flagB) return;
    int b = blockIdx.x;
    const int n = (KPRE - LRANK) * WSTRIDE;
    u64* p = &g_mask[b][LRANK][0];
    for (int i = threadIdx.x; i < n; i += blockDim.x) p[i] = 0ull;
}
__global__ void k_pairsTailF() {
    if (!g_flagB) return;
    int ta = HTILES + blockIdx.x;
    int b = blockIdx.y;
    __shared__ float4 sb4[64];
    __shared__ float  sar[64];
    __shared__ int    srk[64];
    int t = threadIdx.x;
    int row = t & 63;
    int half = t >> 6;
    int sa = ta * 64 + row;
    float4 bi = g_sbox[b][sa];
    float  ai = g_sarea[b][sa];
    int ra = g_srank[b][sa];
    float4 aA = g_aabb[b][ta];
    for (int tb = ta; tb < TILES; tb++) {
        float4 aB = g_aabb[b][tb];
        bool tile_ok = (aA.z > aB.x && aB.z > aA.x && aA.w > aB.y && aB.w > aA.y);
        __syncthreads();
        if (tile_ok && t < 64) {
            int s = tb * 64 + t;
            sb4[t] = g_sbox[b][s];
            sar[t] = g_sarea[b][s];
            srk[t] = g_srank[b][s];
        }
        __syncthreads();
        if (!tile_ok) continue;
        if (!(bi.z > aB.x && aB.z > bi.x && bi.w > aB.y && aB.w > bi.y)) continue;
        bool diag = (ta == tb);
        int j0 = half * 32;
        for (int jj = j0; jj < j0 + 32; ++jj) {
            if (diag && jj <= row) continue;
            float4 bj = sb4[jj];
            float yy1 = fmaxf(bi.x, bj.x);
            float xx1 = fmaxf(bi.y, bj.y);
            float yy2 = fminf(bi.z, bj.z);
            float xx2 = fminf(bi.w, bj.w);
            float dh = __fsub_rn(yy2, yy1);
            float dw = __fsub_rn(xx2, xx1);
            if (dh > 0.f && dw > 0.f) {
                float inter = __fmul_rn(dh, dw);
                float u = __fsub_rn(__fadd_rn(ai, sar[jj]), inter);
                if (u > 0.f) {
                    bool sup;
                    if (inter > __fmul_rn(0.71f, u)) sup = true;
                    else if (inter >= __fmul_rn(0.69f, u)) sup = __fdiv_rn(inter, u) > 0.7f;
                    else sup = false;
                    if (sup) {
                        int rb = srk[jj];
                        int rmin = ra < rb ? ra : rb;
                        int rmax = ra < rb ? rb : ra;
                        atomicOr(&g_mask[b][rmin][rmax >> 6], 1ull << (rmax & 63));
                        atomicOr(&g_rowbits[b][rmin >> 6], 1ull << (rmin & 63));
                    }
                }
            }
        }
    }
}

// ---------------- K10: greedy reduce with bulk selection ----------------
// Rows without a rowbit suppress nobody later -> all valid bits below the first
// suppressor bit in a word are selected en masse (exact greedy order preserved).
__global__ void k_reduce(float* __restrict__ out, int mode) {
    if (mode == 1 && !g_flagB) return;
    int b = blockIdx.x;
    int lane = threadIdx.x;
    __shared__ int sel[KOUT];
    u64 rm0 = 0ull, rm1 = 0ull, rm2 = 0ull;
    const u64* mask = &g_mask[b][0][0];
    u64 hb0 = g_rowbits[b][lane];
    u64 hb1 = g_rowbits[b][lane + 32];
    u64 hb2 = (lane + 64 < WORDS) ? g_rowbits[b][lane + 64] : 0ull;
    int cnt = 0;

    for (int w = 0; w < WORDS && cnt < KOUT; ++w) {
        int slot = w >> 5, owner = w & 31;
        u64 rmv = (slot == 0) ? rm0 : ((slot == 1) ? rm1 : rm2);
        u64 hbv = (slot == 0) ? hb0 : ((slot == 1) ? hb1 : hb2);
        u64 cur = __shfl_sync(0xffffffffu, rmv, owner);
        u64 hasw = __shfl_sync(0xffffffffu, hbv, owner);
        if (w == WORDS - 1) cur |= ~((1ull << 48) - 1);   // rows 6000..6015 invalid

        // prefetch first suppressor rows in this word
        {
            u64 pf = ~cur & hasw;
            #pragma unroll
            for (int c = 0; c < 3; c++) {
                if (!pf) break;
                int nb = __ffsll((long long)pf) - 1;
                pf &= pf - 1;
                const char* p = (const char*)(mask + (size_t)((w << 6) + nb) * WSTRIDE);
                if ((lane >> 3) == c && (lane & 7) < 6)
                    asm volatile("prefetch.global.L1 [%0];" :: "l"(p + (lane & 7) * 128));
            }
        }

        while (cnt < KOUT) {
            u64 valid = ~cur;
            if (!valid) break;
            u64 sup = valid & hasw;
            u64 below = sup ? ((sup & (0ull - sup)) - 1ull) : ~0ull;
            u64 bulk = valid & below;          // non-suppressing selections, in order
            int n = __popcll(bulk);
            int take = n < (KOUT - cnt) ? n : (KOUT - cnt);
            if (take > 0) {
                if (lane == 0) {
                    u64 tb = bulk;
                    int base_ = (w << 6);
                    for (int k = 0; k < take; k++) {
                        int bp = __ffsll((long long)tb) - 1;
                        sel[cnt + k] = base_ + bp;
                        tb &= tb - 1;
                    }
                    if (mode == 0 && w >= (LRANK >> 6)) g_flagB = 1;
                }
                cnt += take;
                cur |= bulk;
                if (cnt >= KOUT) break;
            }
            if (!sup) break;
            // first suppressor row: select it, then apply its suppression row
            int bpos = __ffsll((long long)sup) - 1;
            int i = (w << 6) + bpos;
            if (lane == 0) {
                sel[cnt] = i;
                if (mode == 0 && i >= LRANK) g_flagB = 1;
            }
            cnt++;
            cur |= (1ull << bpos);
            if (cnt >= KOUT) break;
            const u64* rowp = mask + (size_t)i * WSTRIDE;
            u64 r0 = __ldg(rowp + lane);
            u64 r1 = __ldg(rowp + lane + 32);
            u64 r2 = (lane + 64 < WORDS) ? __ldg(rowp + lane + 64) : 0ull;
            u64 rcur = __ldg(rowp + w);        // uniform broadcast, no shfl
            rm0 |= r0; rm1 |= r1; rm2 |= r2;
            cur |= rcur;
            // prefetch next suppressor rows
            u64 pf = ~cur & hasw;
            #pragma unroll
            for (int c = 0; c < 2; c++) {
                if (!pf) break;
                int nb = __ffsll((long long)pf) - 1;
                pf &= pf - 1;
                const char* p = (const char*)(mask + (size_t)((w << 6) + nb) * WSTRIDE);
                if ((lane >> 3) == c && (lane & 7) < 6)
                    asm volatile("prefetch.global.L1 [%0];" :: "l"(p + (lane & 7) * 128));
            }
        }
    }
    __syncwarp();

    float4* o = (float4*)(out + (size_t)b * KOUT * 4);
    for (int r = lane; r < KOUT; r += 32) {
        float4 v = make_float4(0.f, 0.f, 0.f, 0.f);
        if (r < cnt) v = g_boxes[b][sel[r]];
        o[r] = v;
    }
}

// ---------------- launch ----------------
extern "C" void kernel_launch(void* const* d_in, const int* in_sizes, int n_in,
                              void* d_out, int out_size) {
    const float4* scores4 = (const float4*)d_in[0];
    const float4* deltas  = (const float4*)d_in[1];
    const float4* anchors = (const float4*)d_in[2];
    float* out = (float*)d_out;

    k_zero<<<512, 1024>>>();
    {
        dim3 g(256, BATCH);
        k_compactS<<<g, 256>>>(scores4);
    }
    k_check<<<1, 32>>>();
    // gated fallback chain (no-ops when flagA == 0; tiny grids)
    k_zeroF<<<8, 1024>>>();
    {
        dim3 g(16, BATCH);
        k_histF<<<g, 256>>>(scores4);
    }
    k_threshF<<<BATCH, 256>>>();
    {
        dim3 g(16, BATCH);
        k_compactF<<<g, 256>>>(scores4);
    }
    k_refine<<<BATCH, 512>>>();
    {
        dim3 g(NCHUNK2, BATCH);
        k_sort2048<<<g, 1024>>>();
    }
    {
        dim3 g(SORT_N / 256, BATCH);
        k_mergepass<<<g, 256>>>(0, 2048);   // cand2 -> cand
        k_mergepass<<<g, 256>>>(1, 4096);   // cand  -> cand2 (final sorted 8192)
    }
    {
        dim3 g((KPRE + 255) / 256, BATCH);
        k_boxes<<<g, 256>>>(deltas, anchors);
    }
    k_spatial<<<BATCH, 256>>>();
    {
        dim3 g(TILES, HTILES, BATCH);
        k_pairs<<<g, 128>>>();
    }
    k_reduce<<<BATCH, 32>>>(out, 0);
    // gated tail fallback (no-ops when flagB == 0; compact grids)
    k_zeroTailF<<<BATCH, 1024>>>();
    {
        dim3 g(TTILES, BATCH);
        k_pairsTailF<<<g, 128>>>();
    }
    k_reduce<<<BATCH, 32>>>(out, 1);
}